// round 2
// baseline (speedup 1.0000x reference)
#include <cuda_runtime.h>
#include <math.h>

#define BSZ 4
#define NL  512
#define DM  1024
#define NH  16
#define HD  64

// ---------------- scratch (static device globals; no allocation) ----------------
__device__ float g_q[BSZ*NH*NL*HD];        // [b,h,i,d]  8 MB
__device__ float g_k[BSZ*NH*NL*HD];        // [b,h,j,d]  8 MB
__device__ float g_w[BSZ*NH*NL*NL];        // softmax weights [b,h,i,j]  64 MB
__device__ float g_u[BSZ*NH*NL];           // u[b,h,j]
__device__ float g_wvo[NH*DM];             // wvo[h][din]
__device__ float g_bvo[NH];

// ---------------- kernel A: fold wo into wv -> wvo (1024x16) ----------------
// grid (NH, 4), block 256: thread handles one din
__global__ void __launch_bounds__(256) k_wvo(const float* __restrict__ wv,
                                             const float* __restrict__ wo,
                                             const float* __restrict__ bv) {
    int h = blockIdx.x;                        // 0..15
    int din = blockIdx.y * 256 + threadIdx.x;  // 0..1023
    const float* wvrow = wv + (size_t)din * DM + h * HD;
    const float* worow = wo + h * HD;
    float acc = 0.f;
    #pragma unroll
    for (int e = 0; e < HD; e++) acc += wvrow[e] * worow[e];
    g_wvo[h * DM + din] = acc;
    if (din == 0) {
        float bb = 0.f;
        #pragma unroll
        for (int e = 0; e < HD; e++) bb += bv[h * HD + e] * worow[e];
        g_bvo[h] = bb;
    }
}

// ---------------- kernel B: u[b,h,j] = x[b,j,:] @ wvo[h,:] + bvo[h] ----------------
// block 512 = 16 warps, warp h computes head h for row bj
__global__ void __launch_bounds__(512) k_u(const float* __restrict__ x) {
    int bj = blockIdx.x;         // b*NL + j
    int h = threadIdx.x >> 5;    // warp = head (16 warps)
    int lane = threadIdx.x & 31;
    const float* xr = x + (size_t)bj * DM;
    const float* wr = g_wvo + h * DM;
    float acc = 0.f;
    #pragma unroll 8
    for (int t = lane; t < DM; t += 32) acc += xr[t] * wr[t];
    #pragma unroll
    for (int o = 16; o > 0; o >>= 1) acc += __shfl_xor_sync(0xffffffffu, acc, o);
    if (lane == 0) {
        int b = bj >> 9, j = bj & (NL - 1);
        g_u[(b * NH + h) * NL + j] = acc + g_bvo[h];
    }
}

// ---------------- kernel C: Q/K projections (fp32 SGEMM 128x128x8, 8x8/thread) ----
#define BM 128
#define BN 128
#define BK 8
__global__ void __launch_bounds__(256) k_proj(const float* __restrict__ x,
                                              const float* __restrict__ w,
                                              const float* __restrict__ bvec, int which) {
    float* out = which ? g_k : g_q;
    __shared__ float As[BK][BM];
    __shared__ float Bs[BK][BN];
    int tid = threadIdx.x;                 // 256
    int tx = tid & 15, ty = tid >> 4;
    int m0 = blockIdx.y * BM;
    int n0 = blockIdx.x * BN;
    float acc[8][8];
    #pragma unroll
    for (int i = 0; i < 8; i++)
        #pragma unroll
        for (int j = 0; j < 8; j++) acc[i][j] = 0.f;

    int a_k = tid & 7;                     // A loader: 4 rows each
    int a_m = (tid >> 3) * 4;
    int b_k = tid >> 5;                    // B loader: one float4 each
    int b_n = (tid & 31) * 4;

    for (int k0 = 0; k0 < DM; k0 += BK) {
        #pragma unroll
        for (int rr = 0; rr < 4; rr++)
            As[a_k][a_m + rr] = x[(size_t)(m0 + a_m + rr) * DM + k0 + a_k];
        float4 bv4 = *(const float4*)&w[(size_t)(k0 + b_k) * DM + n0 + b_n];
        *(float4*)&Bs[b_k][b_n] = bv4;
        __syncthreads();
        #pragma unroll
        for (int kk = 0; kk < BK; kk++) {
            float av[8], bvv[8];
            *(float4*)&av[0]  = *(const float4*)&As[kk][ty * 8];
            *(float4*)&av[4]  = *(const float4*)&As[kk][ty * 8 + 4];
            *(float4*)&bvv[0] = *(const float4*)&Bs[kk][tx * 8];
            *(float4*)&bvv[4] = *(const float4*)&Bs[kk][tx * 8 + 4];
            #pragma unroll
            for (int i = 0; i < 8; i++)
                #pragma unroll
                for (int j = 0; j < 8; j++)
                    acc[i][j] += av[i] * bvv[j];
        }
        __syncthreads();
    }
    // scatter to [b,h,i,d] layout (+bias)
    #pragma unroll
    for (int i = 0; i < 8; i++) {
        int m = m0 + ty * 8 + i;
        int b = m >> 9, ii = m & (NL - 1);
        #pragma unroll
        for (int j = 0; j < 8; j++) {
            int n = n0 + tx * 8 + j;
            int h = n >> 6, d = n & 63;
            out[((b * NH + h) * NL + ii) * HD + d] = acc[i][j] + bvec[n];
        }
    }
}

// ---------------- kernel D: logits + bias + mask + softmax -> g_w ----------------
// block: 256 thr, one (b, h, 64-row i-tile); smem: qT[64][68] kT[64][68] lg[64][512]
#define QPAD 68
__global__ void __launch_bounds__(256) k_attn(const float* __restrict__ bias,
                                              const int* __restrict__ mask) {
    extern __shared__ float sm[];
    float* qs = sm;                        // [d][i] transposed, pitch 68
    float* ks = sm + HD * QPAD;            // [d][j] transposed, pitch 68
    float* lg = sm + 2 * HD * QPAD;        // [64][512] logits

    int b = blockIdx.z, h = blockIdx.y, i0 = blockIdx.x * 64;
    int tid = threadIdx.x;
    const float* qg = g_q + ((size_t)(b * NH + h) * NL + i0) * HD;
    const float* kg = g_k + (size_t)(b * NH + h) * NL * HD;

    // load q tile transposed
    {
        int rr = tid >> 2, c0 = (tid & 3) * 16;
        #pragma unroll
        for (int c = 0; c < 16; c++)
            qs[(c0 + c) * QPAD + rr] = qg[rr * HD + c0 + c];
    }
    int tx = tid & 15, ty = tid >> 4;
    for (int jt = 0; jt < NL; jt += 64) {
        __syncthreads();
        {
            int rr = tid >> 2, c0 = (tid & 3) * 16;
            #pragma unroll
            for (int c = 0; c < 16; c++)
                ks[(c0 + c) * QPAD + rr] = kg[(jt + rr) * HD + c0 + c];
        }
        __syncthreads();
        float acc[4][4];
        #pragma unroll
        for (int i = 0; i < 4; i++)
            #pragma unroll
            for (int j = 0; j < 4; j++) acc[i][j] = 0.f;
        #pragma unroll 4
        for (int d = 0; d < HD; d++) {
            float4 qa = *(const float4*)&qs[d * QPAD + ty * 4];
            float4 kb = *(const float4*)&ks[d * QPAD + tx * 4];
            float av[4] = {qa.x, qa.y, qa.z, qa.w};
            float bv2[4] = {kb.x, kb.y, kb.z, kb.w};
            #pragma unroll
            for (int i = 0; i < 4; i++)
                #pragma unroll
                for (int j = 0; j < 4; j++)
                    acc[i][j] += av[i] * bv2[j];
        }
        #pragma unroll
        for (int i = 0; i < 4; i++) {
            float4 v = make_float4(acc[i][0], acc[i][1], acc[i][2], acc[i][3]);
            *(float4*)&lg[(ty * 4 + i) * NL + jt + tx * 4] = v;
        }
    }
    __syncthreads();

    // softmax over rows; warp wi handles 8 rows
    const float scale = 0.125f;            // 1/sqrt(64)
    int wi = tid >> 5, lane = tid & 31;
    for (int rr = 0; rr < 8; rr++) {
        int i = wi * 8 + rr;
        int gi = i0 + i;
        const float* brow = bias + ((size_t)(b * NH + h) * NL + gi) * NL;
        const int* mrow = mask + ((size_t)b * NL + gi) * NL;
        float vals[16];
        float m = -3.4e38f;
        #pragma unroll
        for (int t = 0; t < 16; t++) {
            int j = lane + 32 * t;
            float v = lg[i * NL + j] * scale + brow[j];
            if (mrow[j] == 0) v = -1e9f;
            vals[t] = v;
            m = fmaxf(m, v);
        }
        #pragma unroll
        for (int o = 16; o > 0; o >>= 1) m = fmaxf(m, __shfl_xor_sync(0xffffffffu, m, o));
        float s = 0.f;
        #pragma unroll
        for (int t = 0; t < 16; t++) { vals[t] = __expf(vals[t] - m); s += vals[t]; }
        #pragma unroll
        for (int o = 16; o > 0; o >>= 1) s += __shfl_xor_sync(0xffffffffu, s, o);
        float inv = 1.f / s;
        float* wrow = g_w + ((size_t)(b * NH + h) * NL + gi) * NL;
        #pragma unroll
        for (int t = 0; t < 16; t++) wrow[lane + 32 * t] = vals[t] * inv;
    }
}

// ---------------- kernel E: s[j] = sum_h w*u;  force[c] = sum_j r*s + bo ----------
__global__ void __launch_bounds__(256) k_out(const float* __restrict__ r,
                                             const float* __restrict__ bo,
                                             float* __restrict__ out) {
    int bi = blockIdx.x;                   // b*NL + i
    int b = bi >> 9, i = bi & (NL - 1);
    __shared__ float s[NL];
    __shared__ float red[8];
    int tid = threadIdx.x;                 // 256
    for (int j = tid; j < NL; j += 256) {
        float acc = 0.f;
        #pragma unroll
        for (int h = 0; h < NH; h++) {
            acc += g_w[((size_t)(b * NH + h) * NL + i) * NL + j] *
                   g_u[(b * NH + h) * NL + j];
        }
        s[j] = acc;
    }
    __syncthreads();
    for (int c = 0; c < 3; c++) {
        const float* rr = r + ((size_t)(b * 3 + c) * NL + i) * NL;
        float p = 0.f;
        for (int j = tid; j < NL; j += 256) p += rr[j] * s[j];
        #pragma unroll
        for (int o = 16; o > 0; o >>= 1) p += __shfl_xor_sync(0xffffffffu, p, o);
        if ((tid & 31) == 0) red[tid >> 5] = p;
        __syncthreads();
        if (tid == 0) {
            float q = 0.f;
            #pragma unroll
            for (int w = 0; w < 8; w++) q += red[w];
            out[bi * 3 + c] = q + bo[0];
        }
        __syncthreads();
    }
}

// ---------------- launch ----------------
extern "C" void kernel_launch(void* const* d_in, const int* in_sizes, int n_in,
                              void* d_out, int out_size) {
    const float* x    = (const float*)d_in[0];
    const float* r    = (const float*)d_in[1];
    const float* bias = (const float*)d_in[2];
    const int*   mask = (const int*)d_in[3];
    const float* wq   = (const float*)d_in[4];
    const float* bq   = (const float*)d_in[5];
    const float* wk   = (const float*)d_in[6];
    const float* bk   = (const float*)d_in[7];
    const float* wv   = (const float*)d_in[8];
    const float* bv   = (const float*)d_in[9];
    const float* wo   = (const float*)d_in[10];
    const float* bo   = (const float*)d_in[11];
    float* out = (float*)d_out;

    const int attn_smem = (2 * HD * QPAD + 64 * NL) * 4;   // 165,888 B
    static int smem_set = 0;
    // cudaFuncSetAttribute is idempotent and not stream-ordered; calling it
    // every time keeps kernel_launch deterministic.
    cudaFuncSetAttribute(k_attn, cudaFuncAttributeMaxDynamicSharedMemorySize, attn_smem);
    (void)smem_set;

    k_wvo<<<dim3(NH, 4), 256>>>(wv, wo, bv);
    k_u<<<BSZ * NL, 512>>>(x);
    dim3 gProj(DM / BN, (BSZ * NL) / BM);
    k_proj<<<gProj, 256>>>(x, wq, bq, 0);
    k_proj<<<gProj, 256>>>(x, wk, bk, 1);
    k_attn<<<dim3(NL / 64, NH, BSZ), 256, attn_smem>>>(bias, mask);
    k_out<<<BSZ * NL, 256>>>(r, bo, out);
}

// round 3
// speedup vs baseline: 2.2664x; 2.2664x over previous
#include <cuda_runtime.h>
#include <math.h>

#define BSZ 4
#define NL  512
#define DM  1024
#define NH  16
#define HD  64

// ---------------- scratch (static device globals; no allocation) ----------------
__device__ float g_q[BSZ*NH*NL*HD];        // [b,h,i,d]  8 MB
__device__ float g_k[BSZ*NH*NL*HD];        // [b,h,j,d]  8 MB
__device__ float g_w[BSZ*NH*NL*NL];        // softmax weights [b,h,i,j]  64 MB
__device__ float g_u[BSZ*NH*NL];           // u[b,h,j]
__device__ float g_wvo[NH*DM];             // wvo[h][din]
__device__ float g_bvo[NH];

// ---------------- kernel A: fold wo into wv -> wvo (1024x16) ----------------
__global__ void __launch_bounds__(256) k_wvo(const float* __restrict__ wv,
                                             const float* __restrict__ wo,
                                             const float* __restrict__ bv) {
    int h = blockIdx.x;
    int din = blockIdx.y * 256 + threadIdx.x;
    const float* wvrow = wv + (size_t)din * DM + h * HD;
    const float* worow = wo + h * HD;
    float acc = 0.f;
    #pragma unroll
    for (int e = 0; e < HD; e++) acc += wvrow[e] * worow[e];
    g_wvo[h * DM + din] = acc;
    if (din == 0) {
        float bb = 0.f;
        #pragma unroll
        for (int e = 0; e < HD; e++) bb += bv[h * HD + e] * worow[e];
        g_bvo[h] = bb;
    }
}

// ---------------- kernel B: u[b,h,j] = x[b,j,:] @ wvo[h,:] + bvo[h] ----------------
__global__ void __launch_bounds__(512) k_u(const float* __restrict__ x) {
    int bj = blockIdx.x;
    int h = threadIdx.x >> 5;
    int lane = threadIdx.x & 31;
    const float* xr = x + (size_t)bj * DM;
    const float* wr = g_wvo + h * DM;
    float acc = 0.f;
    #pragma unroll 8
    for (int t = lane; t < DM; t += 32) acc += xr[t] * wr[t];
    #pragma unroll
    for (int o = 16; o > 0; o >>= 1) acc += __shfl_xor_sync(0xffffffffu, acc, o);
    if (lane == 0) {
        int b = bj >> 9, j = bj & (NL - 1);
        g_u[(b * NH + h) * NL + j] = acc + g_bvo[h];
    }
}

// ---------------- kernel C: fused Q+K projection ----------------
// SGEMM 128x128x16, double-buffered, 8x8/thread in split 4+4 layout.
// grid (8, 16, 2): z selects {Q, K}.
#define BM 128
#define BN 128
#define BK 16
__global__ void __launch_bounds__(256, 2) k_proj(const float* __restrict__ x,
                                                 const float* __restrict__ wq,
                                                 const float* __restrict__ bq,
                                                 const float* __restrict__ wk,
                                                 const float* __restrict__ bk) {
    const int which = blockIdx.z;
    const float* w    = which ? wk : wq;
    const float* bvec = which ? bk : bq;
    float* out        = which ? g_k : g_q;

    __shared__ float As[2][BK][BM];     // A transposed: As[k][m]
    __shared__ float Bs[2][BK][BN];     // Bs[k][n]

    int tid = threadIdx.x;
    int tx = tid & 15, ty = tid >> 4;
    int m0 = blockIdx.y * BM;
    int n0 = blockIdx.x * BN;

    float acc[8][8];
    #pragma unroll
    for (int i = 0; i < 8; i++)
        #pragma unroll
        for (int j = 0; j < 8; j++) acc[i][j] = 0.f;

    // per-thread load slots: 2 float4 for A, 2 for B per tile
    // A: f in [0,512): row = f>>2 (0..127), chunk = (f&3)*4 -> k offset
    // B: f in [0,512): kk = f>>5 (0..15),  col = (f&31)*4
    float4 pa[2], pb[2];

    {   // prologue: tile 0
        #pragma unroll
        for (int t = 0; t < 2; t++) {
            int f = tid + t * 256;
            int row = f >> 2, ch = (f & 3) * 4;
            pa[t] = *(const float4*)&x[(size_t)(m0 + row) * DM + ch];
            int kk = f >> 5, cc = (f & 31) * 4;
            pb[t] = *(const float4*)&w[(size_t)kk * DM + n0 + cc];
        }
        #pragma unroll
        for (int t = 0; t < 2; t++) {
            int f = tid + t * 256;
            int row = f >> 2, ch = (f & 3) * 4;
            As[0][ch + 0][row] = pa[t].x;
            As[0][ch + 1][row] = pa[t].y;
            As[0][ch + 2][row] = pa[t].z;
            As[0][ch + 3][row] = pa[t].w;
            int kk = f >> 5, cc = (f & 31) * 4;
            *(float4*)&Bs[0][kk][cc] = pb[t];
        }
    }
    __syncthreads();

    int buf = 0;
    for (int k0 = BK; k0 <= DM; k0 += BK) {
        bool more = (k0 < DM);
        if (more) {
            #pragma unroll
            for (int t = 0; t < 2; t++) {
                int f = tid + t * 256;
                int row = f >> 2, ch = (f & 3) * 4;
                pa[t] = *(const float4*)&x[(size_t)(m0 + row) * DM + k0 + ch];
                int kk = f >> 5, cc = (f & 31) * 4;
                pb[t] = *(const float4*)&w[(size_t)(k0 + kk) * DM + n0 + cc];
            }
        }
        #pragma unroll
        for (int kk = 0; kk < BK; kk++) {
            float av[8], bvv[8];
            *(float4*)&av[0]  = *(const float4*)&As[buf][kk][ty * 4];
            *(float4*)&av[4]  = *(const float4*)&As[buf][kk][ty * 4 + 64];
            *(float4*)&bvv[0] = *(const float4*)&Bs[buf][kk][tx * 4];
            *(float4*)&bvv[4] = *(const float4*)&Bs[buf][kk][tx * 4 + 64];
            #pragma unroll
            for (int i = 0; i < 8; i++)
                #pragma unroll
                for (int j = 0; j < 8; j++)
                    acc[i][j] += av[i] * bvv[j];
        }
        if (more) {
            int nb = buf ^ 1;
            #pragma unroll
            for (int t = 0; t < 2; t++) {
                int f = tid + t * 256;
                int row = f >> 2, ch = (f & 3) * 4;
                As[nb][ch + 0][row] = pa[t].x;
                As[nb][ch + 1][row] = pa[t].y;
                As[nb][ch + 2][row] = pa[t].z;
                As[nb][ch + 3][row] = pa[t].w;
                int kk = f >> 5, cc = (f & 31) * 4;
                *(float4*)&Bs[nb][kk][cc] = pb[t];
            }
            __syncthreads();
            buf = nb;
        }
    }

    // epilogue: scatter to [b,h,i,d] layout (+bias)
    #pragma unroll
    for (int ih = 0; ih < 2; ih++) {
        #pragma unroll
        for (int i = 0; i < 4; i++) {
            int m = m0 + ty * 4 + ih * 64 + i;
            int b = m >> 9, ii = m & (NL - 1);
            #pragma unroll
            for (int jh = 0; jh < 2; jh++) {
                #pragma unroll
                for (int j = 0; j < 4; j++) {
                    int n = n0 + tx * 4 + jh * 64 + j;
                    int h = n >> 6, d = n & 63;
                    out[((b * NH + h) * NL + ii) * HD + d] =
                        acc[ih * 4 + i][jh * 4 + j] + bvec[n];
                }
            }
        }
    }
}

// ---------------- kernel D: logits + bias + mask + softmax -> g_w ----------------
// block: 256 thr, one (b, h, 64-row i-tile); j-tile 128, 4x8 acc per thread.
// smem: qs[64][68] + ks[64][132] + lg[64][512]
#define QPAD 68
#define KPAD 132
__global__ void __launch_bounds__(256) k_attn(const float* __restrict__ bias,
                                              const int* __restrict__ mask) {
    extern __shared__ float sm[];
    float* qs = sm;                        // [d][i], pitch QPAD
    float* ks = sm + HD * QPAD;            // [d][j], pitch KPAD
    float* lg = sm + HD * QPAD + HD * KPAD; // [64][512] logits

    int b = blockIdx.z, h = blockIdx.y, i0 = blockIdx.x * 64;
    int tid = threadIdx.x;
    const float* qg = g_q + ((size_t)(b * NH + h) * NL + i0) * HD;
    const float* kg = g_k + (size_t)(b * NH + h) * NL * HD;

    // load q tile transposed: 64 rows x 64 d
    {
        int r = tid >> 2, c0 = (tid & 3) * 16;
        #pragma unroll
        for (int c4 = 0; c4 < 4; c4++) {
            float4 v = *(const float4*)&qg[r * HD + c0 + c4 * 4];
            qs[(c0 + c4 * 4 + 0) * QPAD + r] = v.x;
            qs[(c0 + c4 * 4 + 1) * QPAD + r] = v.y;
            qs[(c0 + c4 * 4 + 2) * QPAD + r] = v.z;
            qs[(c0 + c4 * 4 + 3) * QPAD + r] = v.w;
        }
    }
    int tx = tid & 15, ty = tid >> 4;
    for (int jt = 0; jt < NL; jt += 128) {
        __syncthreads();
        {   // load k tile transposed: 128 rows(j) x 64 d; 2 threads per row
            int r = tid >> 1, c0 = (tid & 1) * 32;
            #pragma unroll
            for (int c4 = 0; c4 < 8; c4++) {
                float4 v = *(const float4*)&kg[(jt + r) * HD + c0 + c4 * 4];
                ks[(c0 + c4 * 4 + 0) * KPAD + r] = v.x;
                ks[(c0 + c4 * 4 + 1) * KPAD + r] = v.y;
                ks[(c0 + c4 * 4 + 2) * KPAD + r] = v.z;
                ks[(c0 + c4 * 4 + 3) * KPAD + r] = v.w;
            }
        }
        __syncthreads();
        float acc[4][8];
        #pragma unroll
        for (int i = 0; i < 4; i++)
            #pragma unroll
            for (int j = 0; j < 8; j++) acc[i][j] = 0.f;
        #pragma unroll 4
        for (int d = 0; d < HD; d++) {
            float av[4], bvv[8];
            *(float4*)&av[0]  = *(const float4*)&qs[d * QPAD + ty * 4];
            *(float4*)&bvv[0] = *(const float4*)&ks[d * KPAD + tx * 4];
            *(float4*)&bvv[4] = *(const float4*)&ks[d * KPAD + tx * 4 + 64];
            #pragma unroll
            for (int i = 0; i < 4; i++)
                #pragma unroll
                for (int j = 0; j < 8; j++)
                    acc[i][j] += av[i] * bvv[j];
        }
        #pragma unroll
        for (int i = 0; i < 4; i++) {
            *(float4*)&lg[(ty * 4 + i) * NL + jt + tx * 4] =
                make_float4(acc[i][0], acc[i][1], acc[i][2], acc[i][3]);
            *(float4*)&lg[(ty * 4 + i) * NL + jt + tx * 4 + 64] =
                make_float4(acc[i][4], acc[i][5], acc[i][6], acc[i][7]);
        }
    }
    __syncthreads();

    // softmax over rows; warp wi handles 8 rows
    const float scale = 0.125f;            // 1/sqrt(64)
    int wi = tid >> 5, lane = tid & 31;
    for (int rr = 0; rr < 8; rr++) {
        int i = wi * 8 + rr;
        int gi = i0 + i;
        const float* brow = bias + ((size_t)(b * NH + h) * NL + gi) * NL;
        const int* mrow = mask + ((size_t)b * NL + gi) * NL;
        float vals[16];
        float m = -3.4e38f;
        #pragma unroll
        for (int t = 0; t < 16; t++) {
            int j = lane + 32 * t;
            float v = lg[i * NL + j] * scale + brow[j];
            if (mrow[j] == 0) v = -1e9f;
            vals[t] = v;
            m = fmaxf(m, v);
        }
        #pragma unroll
        for (int o = 16; o > 0; o >>= 1) m = fmaxf(m, __shfl_xor_sync(0xffffffffu, m, o));
        float s = 0.f;
        #pragma unroll
        for (int t = 0; t < 16; t++) { vals[t] = __expf(vals[t] - m); s += vals[t]; }
        #pragma unroll
        for (int o = 16; o > 0; o >>= 1) s += __shfl_xor_sync(0xffffffffu, s, o);
        float inv = 1.f / s;
        float* wrow = g_w + ((size_t)(b * NH + h) * NL + gi) * NL;
        #pragma unroll
        for (int t = 0; t < 16; t++) wrow[lane + 32 * t] = vals[t] * inv;
    }
}

// ---------------- kernel E: s[j] = sum_h w*u;  force[c] = sum_j r*s + bo ----------
__global__ void __launch_bounds__(256) k_out(const float* __restrict__ r,
                                             const float* __restrict__ bo,
                                             float* __restrict__ out) {
    int bi = blockIdx.x;
    int b = bi >> 9, i = bi & (NL - 1);
    __shared__ float s[NL];
    __shared__ float red[8];
    int tid = threadIdx.x;
    for (int j = tid; j < NL; j += 256) {
        float acc = 0.f;
        #pragma unroll
        for (int h = 0; h < NH; h++) {
            acc += g_w[((size_t)(b * NH + h) * NL + i) * NL + j] *
                   g_u[(b * NH + h) * NL + j];
        }
        s[j] = acc;
    }
    __syncthreads();
    for (int c = 0; c < 3; c++) {
        const float* rr = r + ((size_t)(b * 3 + c) * NL + i) * NL;
        float p = 0.f;
        for (int j = tid; j < NL; j += 256) p += rr[j] * s[j];
        #pragma unroll
        for (int o = 16; o > 0; o >>= 1) p += __shfl_xor_sync(0xffffffffu, p, o);
        if ((tid & 31) == 0) red[tid >> 5] = p;
        __syncthreads();
        if (tid == 0) {
            float q = 0.f;
            #pragma unroll
            for (int w = 0; w < 8; w++) q += red[w];
            out[bi * 3 + c] = q + bo[0];
        }
        __syncthreads();
    }
}

// ---------------- launch ----------------
extern "C" void kernel_launch(void* const* d_in, const int* in_sizes, int n_in,
                              void* d_out, int out_size) {
    const float* x    = (const float*)d_in[0];
    const float* r    = (const float*)d_in[1];
    const float* bias = (const float*)d_in[2];
    const int*   mask = (const int*)d_in[3];
    const float* wq   = (const float*)d_in[4];
    const float* bq   = (const float*)d_in[5];
    const float* wk   = (const float*)d_in[6];
    const float* bk   = (const float*)d_in[7];
    const float* wv   = (const float*)d_in[8];
    const float* bv   = (const float*)d_in[9];
    const float* wo   = (const float*)d_in[10];
    const float* bo   = (const float*)d_in[11];
    float* out = (float*)d_out;

    const int attn_smem = (HD * QPAD + HD * KPAD + 64 * NL) * 4;   // 182,272 B
    cudaFuncSetAttribute(k_attn, cudaFuncAttributeMaxDynamicSharedMemorySize, attn_smem);

    k_wvo<<<dim3(NH, 4), 256>>>(wv, wo, bv);
    k_u<<<BSZ * NL, 512>>>(x);
    k_proj<<<dim3(DM / BN, (BSZ * NL) / BM, 2), 256>>>(x, wq, bq, wk, bk);
    k_attn<<<dim3(NL / 64, NH, BSZ), 256, attn_smem>>>(bias, mask);
    k_out<<<BSZ * NL, 256>>>(r, bo, out);
}

// round 5
// speedup vs baseline: 2.4373x; 1.0754x over previous
#include <cuda_runtime.h>
#include <math.h>

#define BSZ 4
#define NL  512
#define DM  1024
#define NH  16
#define HD  64

// ---------------- scratch (static device globals; no allocation) ----------------
__device__ float g_q[BSZ*NH*NL*HD];        // [b,h,i,d]  8 MB
__device__ float g_k[BSZ*NH*NL*HD];        // [b,h,j,d]  8 MB
__device__ float g_w[BSZ*NH*NL*NL];        // ew[b,h,i,j] = exp(logit)*u[h,j]  64 MB
__device__ float g_irs[BSZ*NH*NL];         // 1/rowsum[b,h,i]
__device__ float g_u[BSZ*NH*NL];           // u[b,h,j]
__device__ float g_wvo[NH*DM];             // wvo[h][din]
__device__ float g_bvo[NH];

// ---------------- kernel A: fold wo into wv -> wvo (1024x16) ----------------
__global__ void __launch_bounds__(256) k_wvo(const float* __restrict__ wv,
                                             const float* __restrict__ wo,
                                             const float* __restrict__ bv) {
    int h = blockIdx.x;
    int din = blockIdx.y * 256 + threadIdx.x;
    const float* wvrow = wv + (size_t)din * DM + h * HD;
    const float* worow = wo + h * HD;
    float acc = 0.f;
    #pragma unroll
    for (int e = 0; e < HD; e++) acc += wvrow[e] * worow[e];
    g_wvo[h * DM + din] = acc;
    if (din == 0) {
        float bb = 0.f;
        #pragma unroll
        for (int e = 0; e < HD; e++) bb += bv[h * HD + e] * worow[e];
        g_bvo[h] = bb;
    }
}

// ---------------- kernel B: u[b,h,j] = x[b,j,:] @ wvo[h,:] + bvo[h] ----------------
__global__ void __launch_bounds__(512) k_u(const float* __restrict__ x) {
    int bj = blockIdx.x;
    int h = threadIdx.x >> 5;
    int lane = threadIdx.x & 31;
    const float* xr = x + (size_t)bj * DM;
    const float* wr = g_wvo + h * DM;
    float acc = 0.f;
    #pragma unroll 8
    for (int t = lane; t < DM; t += 32) acc += xr[t] * wr[t];
    #pragma unroll
    for (int o = 16; o > 0; o >>= 1) acc += __shfl_xor_sync(0xffffffffu, acc, o);
    if (lane == 0) {
        int b = bj >> 9, j = bj & (NL - 1);
        g_u[(b * NH + h) * NL + j] = acc + g_bvo[h];
    }
}

// ---------------- kernel C: fused Q+K projection ----------------
#define BM 128
#define BN 128
#define BK 16
__global__ void __launch_bounds__(256, 2) k_proj(const float* __restrict__ x,
                                                 const float* __restrict__ wq,
                                                 const float* __restrict__ bq,
                                                 const float* __restrict__ wk,
                                                 const float* __restrict__ bk) {
    const int which = blockIdx.z;
    const float* w    = which ? wk : wq;
    const float* bvec = which ? bk : bq;
    float* out        = which ? g_k : g_q;

    __shared__ float As[2][BK][BM];
    __shared__ float Bs[2][BK][BN];

    int tid = threadIdx.x;
    int tx = tid & 15, ty = tid >> 4;
    int m0 = blockIdx.y * BM;
    int n0 = blockIdx.x * BN;

    float acc[8][8];
    #pragma unroll
    for (int i = 0; i < 8; i++)
        #pragma unroll
        for (int j = 0; j < 8; j++) acc[i][j] = 0.f;

    float4 pa[2], pb[2];
    {
        #pragma unroll
        for (int t = 0; t < 2; t++) {
            int f = tid + t * 256;
            int row = f >> 2, ch = (f & 3) * 4;
            pa[t] = *(const float4*)&x[(size_t)(m0 + row) * DM + ch];
            int kk = f >> 5, cc = (f & 31) * 4;
            pb[t] = *(const float4*)&w[(size_t)kk * DM + n0 + cc];
        }
        #pragma unroll
        for (int t = 0; t < 2; t++) {
            int f = tid + t * 256;
            int row = f >> 2, ch = (f & 3) * 4;
            As[0][ch + 0][row] = pa[t].x;
            As[0][ch + 1][row] = pa[t].y;
            As[0][ch + 2][row] = pa[t].z;
            As[0][ch + 3][row] = pa[t].w;
            int kk = f >> 5, cc = (f & 31) * 4;
            *(float4*)&Bs[0][kk][cc] = pb[t];
        }
    }
    __syncthreads();

    int buf = 0;
    for (int k0 = BK; k0 <= DM; k0 += BK) {
        bool more = (k0 < DM);
        if (more) {
            #pragma unroll
            for (int t = 0; t < 2; t++) {
                int f = tid + t * 256;
                int row = f >> 2, ch = (f & 3) * 4;
                pa[t] = *(const float4*)&x[(size_t)(m0 + row) * DM + k0 + ch];
                int kk = f >> 5, cc = (f & 31) * 4;
                pb[t] = *(const float4*)&w[(size_t)(k0 + kk) * DM + n0 + cc];
            }
        }
        #pragma unroll
        for (int kk = 0; kk < BK; kk++) {
            float av[8], bvv[8];
            *(float4*)&av[0]  = *(const float4*)&As[buf][kk][ty * 4];
            *(float4*)&av[4]  = *(const float4*)&As[buf][kk][ty * 4 + 64];
            *(float4*)&bvv[0] = *(const float4*)&Bs[buf][kk][tx * 4];
            *(float4*)&bvv[4] = *(const float4*)&Bs[buf][kk][tx * 4 + 64];
            #pragma unroll
            for (int i = 0; i < 8; i++)
                #pragma unroll
                for (int j = 0; j < 8; j++)
                    acc[i][j] += av[i] * bvv[j];
        }
        if (more) {
            int nb = buf ^ 1;
            #pragma unroll
            for (int t = 0; t < 2; t++) {
                int f = tid + t * 256;
                int row = f >> 2, ch = (f & 3) * 4;
                As[nb][ch + 0][row] = pa[t].x;
                As[nb][ch + 1][row] = pa[t].y;
                As[nb][ch + 2][row] = pa[t].z;
                As[nb][ch + 3][row] = pa[t].w;
                int kk = f >> 5, cc = (f & 31) * 4;
                *(float4*)&Bs[nb][kk][cc] = pb[t];
            }
            __syncthreads();
            buf = nb;
        }
    }

    #pragma unroll
    for (int ih = 0; ih < 2; ih++) {
        #pragma unroll
        for (int i = 0; i < 4; i++) {
            int m = m0 + ty * 4 + ih * 64 + i;
            int b = m >> 9, ii = m & (NL - 1);
            #pragma unroll
            for (int jh = 0; jh < 2; jh++) {
                #pragma unroll
                for (int j = 0; j < 4; j++) {
                    int n = n0 + tx * 4 + jh * 64 + j;
                    int h = n >> 6, d = n & 63;
                    out[((b * NH + h) * NL + ii) * HD + d] =
                        acc[ih * 4 + i][jh * 4 + j] + bvec[n];
                }
            }
        }
    }
}

// ---------------- kernel D: logits -> exp (no max pass) -> ew + rowsums ----------
// block: 256 thr, (b, h, 64-row i-tile); j-tile 128, 4x8 acc per thread.
// No logits buffer: bias/mask/exp fused into GEMM epilogue per j-tile.
// Writes g_w = exp(logit)*u[h,j]  and  g_irs = 1/rowsum.
#define QPAD 68
#define KPAD 132
__global__ void __launch_bounds__(256, 2) k_attn(const float* __restrict__ bias,
                                                 const int* __restrict__ mask) {
    extern __shared__ float sm[];
    float* qs = sm;                        // [d][i], pitch QPAD
    float* ks = sm + HD * QPAD;            // [d][j], pitch KPAD

    int b = blockIdx.z, h = blockIdx.y, i0 = blockIdx.x * 64;
    int tid = threadIdx.x;
    const float* qg = g_q + ((size_t)(b * NH + h) * NL + i0) * HD;
    const float* kg = g_k + (size_t)(b * NH + h) * NL * HD;
    const float* urow = g_u + (size_t)(b * NH + h) * NL;

    // load q tile transposed: 64 rows x 64 d
    {
        int rr = tid >> 2, c0 = (tid & 3) * 16;
        #pragma unroll
        for (int c4 = 0; c4 < 4; c4++) {
            float4 v = *(const float4*)&qg[rr * HD + c0 + c4 * 4];
            qs[(c0 + c4 * 4 + 0) * QPAD + rr] = v.x;
            qs[(c0 + c4 * 4 + 1) * QPAD + rr] = v.y;
            qs[(c0 + c4 * 4 + 2) * QPAD + rr] = v.z;
            qs[(c0 + c4 * 4 + 3) * QPAD + rr] = v.w;
        }
    }
    int tx = tid & 15, ty = tid >> 4;
    const float scale = 0.125f;            // 1/sqrt(64)
    float rs[4] = {0.f, 0.f, 0.f, 0.f};

    for (int jt = 0; jt < NL; jt += 128) {
        __syncthreads();
        {   // load k tile transposed: 128 rows(j) x 64 d; 2 threads per row
            int rr = tid >> 1, c0 = (tid & 1) * 32;
            #pragma unroll
            for (int c4 = 0; c4 < 8; c4++) {
                float4 v = *(const float4*)&kg[(jt + rr) * HD + c0 + c4 * 4];
                ks[(c0 + c4 * 4 + 0) * KPAD + rr] = v.x;
                ks[(c0 + c4 * 4 + 1) * KPAD + rr] = v.y;
                ks[(c0 + c4 * 4 + 2) * KPAD + rr] = v.z;
                ks[(c0 + c4 * 4 + 3) * KPAD + rr] = v.w;
            }
        }
        __syncthreads();
        float acc[4][8];
        #pragma unroll
        for (int i = 0; i < 4; i++)
            #pragma unroll
            for (int j = 0; j < 8; j++) acc[i][j] = 0.f;
        #pragma unroll 4
        for (int d = 0; d < HD; d++) {
            float av[4], bvv[8];
            *(float4*)&av[0]  = *(const float4*)&qs[d * QPAD + ty * 4];
            *(float4*)&bvv[0] = *(const float4*)&ks[d * KPAD + tx * 4];
            *(float4*)&bvv[4] = *(const float4*)&ks[d * KPAD + tx * 4 + 64];
            #pragma unroll
            for (int i = 0; i < 4; i++)
                #pragma unroll
                for (int j = 0; j < 8; j++)
                    acc[i][j] += av[i] * bvv[j];
        }
        // epilogue: bias + mask + exp, fold u, accumulate row sums
        float uv[8];
        #pragma unroll
        for (int c = 0; c < 4; c++) {
            uv[c]     = urow[jt + tx * 4 + c];
            uv[c + 4] = urow[jt + tx * 4 + 64 + c];
        }
        #pragma unroll
        for (int i = 0; i < 4; i++) {
            int gi = i0 + ty * 4 + i;
            const float* brow = bias + ((size_t)(b * NH + h) * NL + gi) * NL + jt;
            const int*   mrow = mask + ((size_t)b * NL + gi) * NL + jt;
            float4 bb0 = *(const float4*)&brow[tx * 4];
            float4 bb1 = *(const float4*)&brow[tx * 4 + 64];
            int4   mm0 = *(const int4*)&mrow[tx * 4];
            int4   mm1 = *(const int4*)&mrow[tx * 4 + 64];
            float e[8];
            e[0] = mm0.x ? __expf(acc[i][0] * scale + bb0.x) : 0.f;
            e[1] = mm0.y ? __expf(acc[i][1] * scale + bb0.y) : 0.f;
            e[2] = mm0.z ? __expf(acc[i][2] * scale + bb0.z) : 0.f;
            e[3] = mm0.w ? __expf(acc[i][3] * scale + bb0.w) : 0.f;
            e[4] = mm1.x ? __expf(acc[i][4] * scale + bb1.x) : 0.f;
            e[5] = mm1.y ? __expf(acc[i][5] * scale + bb1.y) : 0.f;
            e[6] = mm1.z ? __expf(acc[i][6] * scale + bb1.z) : 0.f;
            e[7] = mm1.w ? __expf(acc[i][7] * scale + bb1.w) : 0.f;
            rs[i] += ((e[0] + e[1]) + (e[2] + e[3])) + ((e[4] + e[5]) + (e[6] + e[7]));
            float* wrow = g_w + ((size_t)(b * NH + h) * NL + gi) * NL + jt;
            *(float4*)&wrow[tx * 4] =
                make_float4(e[0] * uv[0], e[1] * uv[1], e[2] * uv[2], e[3] * uv[3]);
            *(float4*)&wrow[tx * 4 + 64] =
                make_float4(e[4] * uv[4], e[5] * uv[5], e[6] * uv[6], e[7] * uv[7]);
        }
    }
    // reduce row sums across the 16 tx threads (xor offsets 1,2,4,8 stay in 16-group)
    #pragma unroll
    for (int i = 0; i < 4; i++) {
        #pragma unroll
        for (int o = 8; o > 0; o >>= 1)
            rs[i] += __shfl_xor_sync(0xffffffffu, rs[i], o);
    }
    if (tx == 0) {
        #pragma unroll
        for (int i = 0; i < 4; i++)
            g_irs[(size_t)(b * NH + h) * NL + i0 + ty * 4 + i] = 1.f / rs[i];
    }
}

// ---------------- kernel E: s[j] = sum_h irs[h]*ew[h,i,j]; force = r @ s + bo ----
__global__ void __launch_bounds__(256) k_out(const float* __restrict__ r,
                                             const float* __restrict__ bo,
                                             float* __restrict__ out) {
    int bi = blockIdx.x;
    int b = bi >> 9, i = bi & (NL - 1);
    __shared__ float s[NL];
    __shared__ float red[8];
    __shared__ float irs_s[NH];
    int tid = threadIdx.x;
    if (tid < NH) irs_s[tid] = g_irs[(size_t)(b * NH + tid) * NL + i];
    __syncthreads();
    for (int j = tid; j < NL; j += 256) {
        float acc = 0.f;
        #pragma unroll
        for (int h = 0; h < NH; h++) {
            acc += g_w[((size_t)(b * NH + h) * NL + i) * NL + j] * irs_s[h];
        }
        s[j] = acc;
    }
    __syncthreads();
    for (int c = 0; c < 3; c++) {
        const float* rr = r + ((size_t)(b * 3 + c) * NL + i) * NL;
        float p = 0.f;
        for (int j = tid; j < NL; j += 256) p += rr[j] * s[j];
        #pragma unroll
        for (int o = 16; o > 0; o >>= 1) p += __shfl_xor_sync(0xffffffffu, p, o);
        if ((tid & 31) == 0) red[tid >> 5] = p;
        __syncthreads();
        if (tid == 0) {
            float q = 0.f;
            #pragma unroll
            for (int w = 0; w < 8; w++) q += red[w];
            out[bi * 3 + c] = q + bo[0];
        }
        __syncthreads();
    }
}

// ---------------- launch ----------------
extern "C" void kernel_launch(void* const* d_in, const int* in_sizes, int n_in,
                              void* d_out, int out_size) {
    const float* x    = (const float*)d_in[0];
    const float* r    = (const float*)d_in[1];
    const float* bias = (const float*)d_in[2];
    const int*   mask = (const int*)d_in[3];
    const float* wq   = (const float*)d_in[4];
    const float* bq   = (const float*)d_in[5];
    const float* wk   = (const float*)d_in[6];
    const float* bk   = (const float*)d_in[7];
    const float* wv   = (const float*)d_in[8];
    const float* bv   = (const float*)d_in[9];
    const float* wo   = (const float*)d_in[10];
    const float* bo   = (const float*)d_in[11];
    float* out = (float*)d_out;

    const int attn_smem = (HD * QPAD + HD * KPAD) * 4;   // 51,200 B
    cudaFuncSetAttribute(k_attn, cudaFuncAttributeMaxDynamicSharedMemorySize, attn_smem);

    k_wvo<<<dim3(NH, 4), 256>>>(wv, wo, bv);
    k_u<<<BSZ * NL, 512>>>(x);
    k_proj<<<dim3(DM / BN, (BSZ * NL) / BM, 2), 256>>>(x, wq, bq, wk, bk);
    k_attn<<<dim3(NL / 64, NH, BSZ), 256, attn_smem>>>(bias, mask);
    k_out<<<BSZ * NL, 256>>>(r, bo, out);
}

// round 6
// speedup vs baseline: 2.5057x; 1.0281x over previous
#include <cuda_runtime.h>
#include <math.h>

#define BSZ 4
#define NL  512
#define DM  1024
#define NH  16
#define HD  64

// ---------------- scratch (static device globals; no allocation) ----------------
__device__ float g_q[BSZ*NH*NL*HD];        // [b,h,i,d]  8 MB
__device__ float g_k[BSZ*NH*NL*HD];        // [b,h,j,d]  8 MB
__device__ float g_w[BSZ*NH*NL*NL];        // ew[b,h,i,j] = exp(logit)*u[h,j]  64 MB
__device__ float g_irs[BSZ*NH*NL];         // 1/rowsum[b,h,i]
__device__ float g_u[BSZ*NH*NL];           // u[b,h,j]
__device__ float g_wvo[NH*DM];             // wvo[h][din]
__device__ float g_bvo[NH];

// ---------------- kernel A: fold wo into wv -> wvo (1024x16) ----------------
__global__ void __launch_bounds__(256) k_wvo(const float* __restrict__ wv,
                                             const float* __restrict__ wo,
                                             const float* __restrict__ bv) {
    int h = blockIdx.x;
    int din = blockIdx.y * 256 + threadIdx.x;
    const float* wvrow = wv + (size_t)din * DM + h * HD;
    const float* worow = wo + h * HD;
    float acc = 0.f;
    #pragma unroll
    for (int e = 0; e < HD; e++) acc += wvrow[e] * worow[e];
    g_wvo[h * DM + din] = acc;
    if (din == 0) {
        float bb = 0.f;
        #pragma unroll
        for (int e = 0; e < HD; e++) bb += bv[h * HD + e] * worow[e];
        g_bvo[h] = bb;
    }
}

// ---------------- kernel B: u[b,h,j] = x[b,j,:] @ wvo[h,:] + bvo[h] ----------------
// x row staged in smem once; 16 warps (one per head) dot against it.
__global__ void __launch_bounds__(512) k_u(const float* __restrict__ x) {
    int bj = blockIdx.x;
    __shared__ float xs[DM];
    int tid = threadIdx.x;
    if (tid < 256) ((float4*)xs)[tid] = ((const float4*)(x + (size_t)bj * DM))[tid];
    __syncthreads();
    int h = tid >> 5;
    int lane = tid & 31;
    const float* wr = g_wvo + h * DM;
    float acc = 0.f;
    #pragma unroll 8
    for (int t = lane; t < DM; t += 32) acc += xs[t] * wr[t];
    #pragma unroll
    for (int o = 16; o > 0; o >>= 1) acc += __shfl_xor_sync(0xffffffffu, acc, o);
    if (lane == 0) {
        int b = bj >> 9, j = bj & (NL - 1);
        g_u[(b * NH + h) * NL + j] = acc + g_bvo[h];
    }
}

// ---------------- kernel C: fused Q+K projection ----------------
#define BM 128
#define BN 128
#define BK 16
__global__ void __launch_bounds__(256, 2) k_proj(const float* __restrict__ x,
                                                 const float* __restrict__ wq,
                                                 const float* __restrict__ bq,
                                                 const float* __restrict__ wk,
                                                 const float* __restrict__ bk) {
    const int which = blockIdx.z;
    const float* w    = which ? wk : wq;
    const float* bvec = which ? bk : bq;
    float* out        = which ? g_k : g_q;

    __shared__ float As[2][BK][BM];
    __shared__ float Bs[2][BK][BN];

    int tid = threadIdx.x;
    int tx = tid & 15, ty = tid >> 4;
    int m0 = blockIdx.y * BM;
    int n0 = blockIdx.x * BN;

    float acc[8][8];
    #pragma unroll
    for (int i = 0; i < 8; i++)
        #pragma unroll
        for (int j = 0; j < 8; j++) acc[i][j] = 0.f;

    float4 pa[2], pb[2];
    {
        #pragma unroll
        for (int t = 0; t < 2; t++) {
            int f = tid + t * 256;
            int row = f >> 2, ch = (f & 3) * 4;
            pa[t] = *(const float4*)&x[(size_t)(m0 + row) * DM + ch];
            int kk = f >> 5, cc = (f & 31) * 4;
            pb[t] = *(const float4*)&w[(size_t)kk * DM + n0 + cc];
        }
        #pragma unroll
        for (int t = 0; t < 2; t++) {
            int f = tid + t * 256;
            int row = f >> 2, ch = (f & 3) * 4;
            As[0][ch + 0][row] = pa[t].x;
            As[0][ch + 1][row] = pa[t].y;
            As[0][ch + 2][row] = pa[t].z;
            As[0][ch + 3][row] = pa[t].w;
            int kk = f >> 5, cc = (f & 31) * 4;
            *(float4*)&Bs[0][kk][cc] = pb[t];
        }
    }
    __syncthreads();

    int buf = 0;
    for (int k0 = BK; k0 <= DM; k0 += BK) {
        bool more = (k0 < DM);
        if (more) {
            #pragma unroll
            for (int t = 0; t < 2; t++) {
                int f = tid + t * 256;
                int row = f >> 2, ch = (f & 3) * 4;
                pa[t] = *(const float4*)&x[(size_t)(m0 + row) * DM + k0 + ch];
                int kk = f >> 5, cc = (f & 31) * 4;
                pb[t] = *(const float4*)&w[(size_t)(k0 + kk) * DM + n0 + cc];
            }
        }
        #pragma unroll
        for (int kk = 0; kk < BK; kk++) {
            float av[8], bvv[8];
            *(float4*)&av[0]  = *(const float4*)&As[buf][kk][ty * 4];
            *(float4*)&av[4]  = *(const float4*)&As[buf][kk][ty * 4 + 64];
            *(float4*)&bvv[0] = *(const float4*)&Bs[buf][kk][tx * 4];
            *(float4*)&bvv[4] = *(const float4*)&Bs[buf][kk][tx * 4 + 64];
            #pragma unroll
            for (int i = 0; i < 8; i++)
                #pragma unroll
                for (int j = 0; j < 8; j++)
                    acc[i][j] += av[i] * bvv[j];
        }
        if (more) {
            int nb = buf ^ 1;
            #pragma unroll
            for (int t = 0; t < 2; t++) {
                int f = tid + t * 256;
                int row = f >> 2, ch = (f & 3) * 4;
                As[nb][ch + 0][row] = pa[t].x;
                As[nb][ch + 1][row] = pa[t].y;
                As[nb][ch + 2][row] = pa[t].z;
                As[nb][ch + 3][row] = pa[t].w;
                int kk = f >> 5, cc = (f & 31) * 4;
                *(float4*)&Bs[nb][kk][cc] = pb[t];
            }
            __syncthreads();
            buf = nb;
        }
    }

    #pragma unroll
    for (int ih = 0; ih < 2; ih++) {
        #pragma unroll
        for (int i = 0; i < 4; i++) {
            int m = m0 + ty * 4 + ih * 64 + i;
            int b = m >> 9, ii = m & (NL - 1);
            #pragma unroll
            for (int jh = 0; jh < 2; jh++) {
                #pragma unroll
                for (int j = 0; j < 4; j++) {
                    int n = n0 + tx * 4 + jh * 64 + j;
                    int h = n >> 6, d = n & 63;
                    out[((b * NH + h) * NL + ii) * HD + d] =
                        acc[ih * 4 + i][jh * 4 + j] + bvec[n];
                }
            }
        }
    }
}

// ---------------- kernel D: logits -> exp (no max pass) -> ew + rowsums ----------
// scale folded into q smem; forced 3 blocks/SM for latency hiding.
#define QPAD 68
#define KPAD 132
__global__ void __launch_bounds__(256, 3) k_attn(const float* __restrict__ bias,
                                                 const int* __restrict__ mask) {
    extern __shared__ float sm[];
    float* qs = sm;                        // [d][i], pitch QPAD (pre-scaled)
    float* ks = sm + HD * QPAD;            // [d][j], pitch KPAD

    int b = blockIdx.z, h = blockIdx.y, i0 = blockIdx.x * 64;
    int tid = threadIdx.x;
    const float* qg = g_q + ((size_t)(b * NH + h) * NL + i0) * HD;
    const float* kg = g_k + (size_t)(b * NH + h) * NL * HD;
    const float* urow = g_u + (size_t)(b * NH + h) * NL;
    const float scale = 0.125f;            // 1/sqrt(64)

    // load q tile transposed, pre-scaled
    {
        int rr = tid >> 2, c0 = (tid & 3) * 16;
        #pragma unroll
        for (int c4 = 0; c4 < 4; c4++) {
            float4 v = *(const float4*)&qg[rr * HD + c0 + c4 * 4];
            qs[(c0 + c4 * 4 + 0) * QPAD + rr] = v.x * scale;
            qs[(c0 + c4 * 4 + 1) * QPAD + rr] = v.y * scale;
            qs[(c0 + c4 * 4 + 2) * QPAD + rr] = v.z * scale;
            qs[(c0 + c4 * 4 + 3) * QPAD + rr] = v.w * scale;
        }
    }
    int tx = tid & 15, ty = tid >> 4;
    float rs[4] = {0.f, 0.f, 0.f, 0.f};

    for (int jt = 0; jt < NL; jt += 128) {
        __syncthreads();
        {   // load k tile transposed: 128 rows(j) x 64 d; 2 threads per row
            int rr = tid >> 1, c0 = (tid & 1) * 32;
            #pragma unroll
            for (int c4 = 0; c4 < 8; c4++) {
                float4 v = *(const float4*)&kg[(jt + rr) * HD + c0 + c4 * 4];
                ks[(c0 + c4 * 4 + 0) * KPAD + rr] = v.x;
                ks[(c0 + c4 * 4 + 1) * KPAD + rr] = v.y;
                ks[(c0 + c4 * 4 + 2) * KPAD + rr] = v.z;
                ks[(c0 + c4 * 4 + 3) * KPAD + rr] = v.w;
            }
        }
        __syncthreads();
        float acc[4][8];
        #pragma unroll
        for (int i = 0; i < 4; i++)
            #pragma unroll
            for (int j = 0; j < 8; j++) acc[i][j] = 0.f;
        #pragma unroll 4
        for (int d = 0; d < HD; d++) {
            float av[4], bvv[8];
            *(float4*)&av[0]  = *(const float4*)&qs[d * QPAD + ty * 4];
            *(float4*)&bvv[0] = *(const float4*)&ks[d * KPAD + tx * 4];
            *(float4*)&bvv[4] = *(const float4*)&ks[d * KPAD + tx * 4 + 64];
            #pragma unroll
            for (int i = 0; i < 4; i++)
                #pragma unroll
                for (int j = 0; j < 8; j++)
                    acc[i][j] += av[i] * bvv[j];
        }
        // epilogue: bias + mask + exp, fold u, accumulate row sums
        float uv[8];
        #pragma unroll
        for (int c = 0; c < 4; c++) {
            uv[c]     = urow[jt + tx * 4 + c];
            uv[c + 4] = urow[jt + tx * 4 + 64 + c];
        }
        #pragma unroll
        for (int i = 0; i < 4; i++) {
            int gi = i0 + ty * 4 + i;
            const float* brow = bias + ((size_t)(b * NH + h) * NL + gi) * NL + jt;
            const int*   mrow = mask + ((size_t)b * NL + gi) * NL + jt;
            float4 bb0 = *(const float4*)&brow[tx * 4];
            float4 bb1 = *(const float4*)&brow[tx * 4 + 64];
            int4   mm0 = *(const int4*)&mrow[tx * 4];
            int4   mm1 = *(const int4*)&mrow[tx * 4 + 64];
            float e[8];
            e[0] = mm0.x ? __expf(acc[i][0] + bb0.x) : 0.f;
            e[1] = mm0.y ? __expf(acc[i][1] + bb0.y) : 0.f;
            e[2] = mm0.z ? __expf(acc[i][2] + bb0.z) : 0.f;
            e[3] = mm0.w ? __expf(acc[i][3] + bb0.w) : 0.f;
            e[4] = mm1.x ? __expf(acc[i][4] + bb1.x) : 0.f;
            e[5] = mm1.y ? __expf(acc[i][5] + bb1.y) : 0.f;
            e[6] = mm1.z ? __expf(acc[i][6] + bb1.z) : 0.f;
            e[7] = mm1.w ? __expf(acc[i][7] + bb1.w) : 0.f;
            rs[i] += ((e[0] + e[1]) + (e[2] + e[3])) + ((e[4] + e[5]) + (e[6] + e[7]));
            float* wrow = g_w + ((size_t)(b * NH + h) * NL + gi) * NL + jt;
            *(float4*)&wrow[tx * 4] =
                make_float4(e[0] * uv[0], e[1] * uv[1], e[2] * uv[2], e[3] * uv[3]);
            *(float4*)&wrow[tx * 4 + 64] =
                make_float4(e[4] * uv[4], e[5] * uv[5], e[6] * uv[6], e[7] * uv[7]);
        }
    }
    // reduce row sums across the 16 tx threads
    #pragma unroll
    for (int i = 0; i < 4; i++) {
        #pragma unroll
        for (int o = 8; o > 0; o >>= 1)
            rs[i] += __shfl_xor_sync(0xffffffffu, rs[i], o);
    }
    if (tx == 0) {
        #pragma unroll
        for (int i = 0; i < 4; i++)
            g_irs[(size_t)(b * NH + h) * NL + i0 + ty * 4 + i] = 1.f / rs[i];
    }
}

// ---------------- kernel E: s[j] = sum_h irs[h]*ew[h,i,j]; force = r @ s + bo ----
// 128 threads/block, float4 per thread, 16-way unrolled h loop (MLP 16).
__global__ void __launch_bounds__(128) k_out(const float* __restrict__ r,
                                             const float* __restrict__ bo,
                                             float* __restrict__ out) {
    int bi = blockIdx.x;
    int b = bi >> 9, i = bi & (NL - 1);
    __shared__ float4 s4[NL / 4];          // 128 float4
    __shared__ float irs_s[NH];
    __shared__ float red[3][4];
    int tid = threadIdx.x;
    if (tid < NH) irs_s[tid] = g_irs[(size_t)(b * NH + tid) * NL + i];
    __syncthreads();

    const float* wbase = g_w + ((size_t)(b * NH) * NL + i) * NL;
    float4 a = make_float4(0.f, 0.f, 0.f, 0.f);
    #pragma unroll
    for (int h = 0; h < NH; h++) {
        float4 wv4 = ((const float4*)(wbase + (size_t)h * NL * NL))[tid];
        float ir = irs_s[h];
        a.x += ir * wv4.x; a.y += ir * wv4.y;
        a.z += ir * wv4.z; a.w += ir * wv4.w;
    }
    s4[tid] = a;
    __syncthreads();

    float p[3];
    #pragma unroll
    for (int c = 0; c < 3; c++) {
        const float4* rr = (const float4*)(r + ((size_t)(b * 3 + c) * NL + i) * NL);
        float4 rv = rr[tid];
        float4 sv = s4[tid];
        p[c] = rv.x * sv.x + rv.y * sv.y + rv.z * sv.z + rv.w * sv.w;
    }
    int lane = tid & 31, wrp = tid >> 5;
    #pragma unroll
    for (int c = 0; c < 3; c++) {
        #pragma unroll
        for (int o = 16; o > 0; o >>= 1)
            p[c] += __shfl_xor_sync(0xffffffffu, p[c], o);
        if (lane == 0) red[c][wrp] = p[c];
    }
    __syncthreads();
    if (tid < 3)
        out[bi * 3 + tid] = red[tid][0] + red[tid][1] + red[tid][2] + red[tid][3] + bo[0];
}

// ---------------- launch ----------------
extern "C" void kernel_launch(void* const* d_in, const int* in_sizes, int n_in,
                              void* d_out, int out_size) {
    const float* x    = (const float*)d_in[0];
    const float* r    = (const float*)d_in[1];
    const float* bias = (const float*)d_in[2];
    const int*   mask = (const int*)d_in[3];
    const float* wq   = (const float*)d_in[4];
    const float* bq   = (const float*)d_in[5];
    const float* wk   = (const float*)d_in[6];
    const float* bk   = (const float*)d_in[7];
    const float* wv   = (const float*)d_in[8];
    const float* bv   = (const float*)d_in[9];
    const float* wo   = (const float*)d_in[10];
    const float* bo   = (const float*)d_in[11];
    float* out = (float*)d_out;

    const int attn_smem = (HD * QPAD + HD * KPAD) * 4;   // 51,200 B
    cudaFuncSetAttribute(k_attn, cudaFuncAttributeMaxDynamicSharedMemorySize, attn_smem);

    k_wvo<<<dim3(NH, 4), 256>>>(wv, wo, bv);
    k_u<<<BSZ * NL, 512>>>(x);
    k_proj<<<dim3(DM / BN, (BSZ * NL) / BM, 2), 256>>>(x, wq, bq, wk, bk);
    k_attn<<<dim3(NL / 64, NH, BSZ), 256, attn_smem>>>(bias, mask);
    k_out<<<BSZ * NL, 128>>>(r, bo, out);
}

// round 8
// speedup vs baseline: 2.6007x; 1.0379x over previous
#include <cuda_runtime.h>
#include <math.h>

#define BSZ 4
#define NL  512
#define DM  1024
#define NH  16
#define HD  64

// ---------------- scratch (static device globals; no allocation) ----------------
__device__ float g_q[BSZ*NH*NL*HD];        // [b,h,i,d]  8 MB
__device__ float g_k[BSZ*NH*NL*HD];        // [b,h,j,d]  8 MB
__device__ float g_w[BSZ*NH*NL*NL];        // ew[b,h,i,j] = exp(logit)*u[h,j]  64 MB
__device__ float g_irs[BSZ*NH*NL];         // 1/rowsum[b,h,i]
__device__ float g_u[BSZ*NH*NL];           // u[b,h,j]
__device__ float g_wvo[NH*DM];             // wvo[h][din]
__device__ float g_bvo[NH];

// ---------------- kernel A: fold wo into wv -> wvo (1024x16) ----------------
__global__ void __launch_bounds__(256) k_wvo(const float* __restrict__ wv,
                                             const float* __restrict__ wo,
                                             const float* __restrict__ bv) {
    int h = blockIdx.x;
    int din = blockIdx.y * 256 + threadIdx.x;
    const float* wvrow = wv + (size_t)din * DM + h * HD;
    const float* worow = wo + h * HD;
    float acc = 0.f;
    #pragma unroll
    for (int e = 0; e < HD; e++) acc += wvrow[e] * worow[e];
    g_wvo[h * DM + din] = acc;
    if (din == 0) {
        float bb = 0.f;
        #pragma unroll
        for (int e = 0; e < HD; e++) bb += bv[h * HD + e] * worow[e];
        g_bvo[h] = bb;
    }
}

// ---------------- kernel B: u[b,h,j] = x[b,j,:] @ wvo[h,:] + bvo[h] ----------------
__global__ void __launch_bounds__(512) k_u(const float* __restrict__ x) {
    int bj = blockIdx.x;
    __shared__ float xs[DM];
    int tid = threadIdx.x;
    if (tid < 256) ((float4*)xs)[tid] = ((const float4*)(x + (size_t)bj * DM))[tid];
    __syncthreads();
    int h = tid >> 5;
    int lane = tid & 31;
    const float* wr = g_wvo + h * DM;
    float acc = 0.f;
    #pragma unroll 8
    for (int t = lane; t < DM; t += 32) acc += xs[t] * wr[t];
    #pragma unroll
    for (int o = 16; o > 0; o >>= 1) acc += __shfl_xor_sync(0xffffffffu, acc, o);
    if (lane == 0) {
        int b = bj >> 9, j = bj & (NL - 1);
        g_u[(b * NH + h) * NL + j] = acc + g_bvo[h];
    }
}

// ---------------- kernel C: fused Q+K projection ----------------
#define BM 128
#define BN 128
#define BK 16
__global__ void __launch_bounds__(256, 2) k_proj(const float* __restrict__ x,
                                                 const float* __restrict__ wq,
                                                 const float* __restrict__ bq,
                                                 const float* __restrict__ wk,
                                                 const float* __restrict__ bk) {
    const int which = blockIdx.z;
    const float* w    = which ? wk : wq;
    const float* bvec = which ? bk : bq;
    float* out        = which ? g_k : g_q;

    __shared__ float As[2][BK][BM];
    __shared__ float Bs[2][BK][BN];

    int tid = threadIdx.x;
    int tx = tid & 15, ty = tid >> 4;
    int m0 = blockIdx.y * BM;
    int n0 = blockIdx.x * BN;

    float acc[8][8];
    #pragma unroll
    for (int i = 0; i < 8; i++)
        #pragma unroll
        for (int j = 0; j < 8; j++) acc[i][j] = 0.f;

    float4 pa[2], pb[2];
    {
        #pragma unroll
        for (int t = 0; t < 2; t++) {
            int f = tid + t * 256;
            int row = f >> 2, ch = (f & 3) * 4;
            pa[t] = *(const float4*)&x[(size_t)(m0 + row) * DM + ch];
            int kk = f >> 5, cc = (f & 31) * 4;
            pb[t] = *(const float4*)&w[(size_t)kk * DM + n0 + cc];
        }
        #pragma unroll
        for (int t = 0; t < 2; t++) {
            int f = tid + t * 256;
            int row = f >> 2, ch = (f & 3) * 4;
            As[0][ch + 0][row] = pa[t].x;
            As[0][ch + 1][row] = pa[t].y;
            As[0][ch + 2][row] = pa[t].z;
            As[0][ch + 3][row] = pa[t].w;
            int kk = f >> 5, cc = (f & 31) * 4;
            *(float4*)&Bs[0][kk][cc] = pb[t];
        }
    }
    __syncthreads();

    int buf = 0;
    for (int k0 = BK; k0 <= DM; k0 += BK) {
        bool more = (k0 < DM);
        if (more) {
            #pragma unroll
            for (int t = 0; t < 2; t++) {
                int f = tid + t * 256;
                int row = f >> 2, ch = (f & 3) * 4;
                pa[t] = *(const float4*)&x[(size_t)(m0 + row) * DM + k0 + ch];
                int kk = f >> 5, cc = (f & 31) * 4;
                pb[t] = *(const float4*)&w[(size_t)(k0 + kk) * DM + n0 + cc];
            }
        }
        #pragma unroll
        for (int kk = 0; kk < BK; kk++) {
            float av[8], bvv[8];
            *(float4*)&av[0]  = *(const float4*)&As[buf][kk][ty * 4];
            *(float4*)&av[4]  = *(const float4*)&As[buf][kk][ty * 4 + 64];
            *(float4*)&bvv[0] = *(const float4*)&Bs[buf][kk][tx * 4];
            *(float4*)&bvv[4] = *(const float4*)&Bs[buf][kk][tx * 4 + 64];
            #pragma unroll
            for (int i = 0; i < 8; i++)
                #pragma unroll
                for (int j = 0; j < 8; j++)
                    acc[i][j] += av[i] * bvv[j];
        }
        if (more) {
            int nb = buf ^ 1;
            #pragma unroll
            for (int t = 0; t < 2; t++) {
                int f = tid + t * 256;
                int row = f >> 2, ch = (f & 3) * 4;
                As[nb][ch + 0][row] = pa[t].x;
                As[nb][ch + 1][row] = pa[t].y;
                As[nb][ch + 2][row] = pa[t].z;
                As[nb][ch + 3][row] = pa[t].w;
                int kk = f >> 5, cc = (f & 31) * 4;
                *(float4*)&Bs[nb][kk][cc] = pb[t];
            }
            __syncthreads();
            buf = nb;
        }
    }

    #pragma unroll
    for (int ih = 0; ih < 2; ih++) {
        #pragma unroll
        for (int i = 0; i < 4; i++) {
            int m = m0 + ty * 4 + ih * 64 + i;
            int b = m >> 9, ii = m & (NL - 1);
            #pragma unroll
            for (int jh = 0; jh < 2; jh++) {
                #pragma unroll
                for (int j = 0; j < 4; j++) {
                    int n = n0 + tx * 4 + jh * 64 + j;
                    int h = n >> 6, d = n & 63;
                    out[((b * NH + h) * NL + ii) * HD + d] =
                        acc[ih * 4 + i][jh * 4 + j] + bvec[n];
                }
            }
        }
    }
}

// ---------------- kernel D: logits -> exp (no max pass) -> ew + rowsums ----------
// 128x128 block tile, 8x8 per thread: 4 LDS.128 per 64 FMA (balanced pipes).
#define APAD 132
__global__ void __launch_bounds__(256, 2) k_attn(const float* __restrict__ bias,
                                                 const int* __restrict__ mask) {
    extern __shared__ float sm[];
    float* qs = sm;                        // [d][i], pitch APAD (pre-scaled)
    float* ks = sm + HD * APAD;            // [d][j], pitch APAD

    int b = blockIdx.z, h = blockIdx.y, i0 = blockIdx.x * 128;
    int tid = threadIdx.x;
    const float* qg = g_q + ((size_t)(b * NH + h) * NL + i0) * HD;
    const float* kg = g_k + (size_t)(b * NH + h) * NL * HD;
    const float* urow = g_u + (size_t)(b * NH + h) * NL;
    const float scale = 0.125f;            // 1/sqrt(64)

    // load q tile transposed (128 rows x 64 d), pre-scaled; 2 threads per row
    {
        int rr = tid >> 1, c0 = (tid & 1) * 32;
        #pragma unroll
        for (int c4 = 0; c4 < 8; c4++) {
            float4 v = *(const float4*)&qg[rr * HD + c0 + c4 * 4];
            qs[(c0 + c4 * 4 + 0) * APAD + rr] = v.x * scale;
            qs[(c0 + c4 * 4 + 1) * APAD + rr] = v.y * scale;
            qs[(c0 + c4 * 4 + 2) * APAD + rr] = v.z * scale;
            qs[(c0 + c4 * 4 + 3) * APAD + rr] = v.w * scale;
        }
    }
    int tx = tid & 15, ty = tid >> 4;
    float rs[8] = {0.f, 0.f, 0.f, 0.f, 0.f, 0.f, 0.f, 0.f};

    for (int jt = 0; jt < NL; jt += 128) {
        __syncthreads();
        {   // load k tile transposed (128 rows(j) x 64 d); 2 threads per row
            int rr = tid >> 1, c0 = (tid & 1) * 32;
            #pragma unroll
            for (int c4 = 0; c4 < 8; c4++) {
                float4 v = *(const float4*)&kg[(jt + rr) * HD + c0 + c4 * 4];
                ks[(c0 + c4 * 4 + 0) * APAD + rr] = v.x;
                ks[(c0 + c4 * 4 + 1) * APAD + rr] = v.y;
                ks[(c0 + c4 * 4 + 2) * APAD + rr] = v.z;
                ks[(c0 + c4 * 4 + 3) * APAD + rr] = v.w;
            }
        }
        __syncthreads();
        float acc[8][8];
        #pragma unroll
        for (int i = 0; i < 8; i++)
            #pragma unroll
            for (int j = 0; j < 8; j++) acc[i][j] = 0.f;
        #pragma unroll 2
        for (int d = 0; d < HD; d++) {
            float av[8], bvv[8];
            *(float4*)&av[0]  = *(const float4*)&qs[d * APAD + ty * 4];
            *(float4*)&av[4]  = *(const float4*)&qs[d * APAD + ty * 4 + 64];
            *(float4*)&bvv[0] = *(const float4*)&ks[d * APAD + tx * 4];
            *(float4*)&bvv[4] = *(const float4*)&ks[d * APAD + tx * 4 + 64];
            #pragma unroll
            for (int i = 0; i < 8; i++)
                #pragma unroll
                for (int j = 0; j < 8; j++)
                    acc[i][j] += av[i] * bvv[j];
        }
        // epilogue: bias + mask + exp, fold u, accumulate row sums
        float uv[8];
        #pragma unroll
        for (int c = 0; c < 4; c++) {
            uv[c]     = urow[jt + tx * 4 + c];
            uv[c + 4] = urow[jt + tx * 4 + 64 + c];
        }
        #pragma unroll
        for (int ih = 0; ih < 2; ih++) {
            #pragma unroll
            for (int i = 0; i < 4; i++) {
                int ai = ih * 4 + i;
                int gi = i0 + ih * 64 + ty * 4 + i;
                const float* brow = bias + ((size_t)(b * NH + h) * NL + gi) * NL + jt;
                const int*   mrow = mask + ((size_t)b * NL + gi) * NL + jt;
                float4 bb0 = *(const float4*)&brow[tx * 4];
                float4 bb1 = *(const float4*)&brow[tx * 4 + 64];
                int4   mm0 = *(const int4*)&mrow[tx * 4];
                int4   mm1 = *(const int4*)&mrow[tx * 4 + 64];
                float e[8];
                e[0] = mm0.x ? __expf(acc[ai][0] + bb0.x) : 0.f;
                e[1] = mm0.y ? __expf(acc[ai][1] + bb0.y) : 0.f;
                e[2] = mm0.z ? __expf(acc[ai][2] + bb0.z) : 0.f;
                e[3] = mm0.w ? __expf(acc[ai][3] + bb0.w) : 0.f;
                e[4] = mm1.x ? __expf(acc[ai][4] + bb1.x) : 0.f;
                e[5] = mm1.y ? __expf(acc[ai][5] + bb1.y) : 0.f;
                e[6] = mm1.z ? __expf(acc[ai][6] + bb1.z) : 0.f;
                e[7] = mm1.w ? __expf(acc[ai][7] + bb1.w) : 0.f;
                rs[ai] += ((e[0] + e[1]) + (e[2] + e[3])) +
                          ((e[4] + e[5]) + (e[6] + e[7]));
                float* wrow = g_w + ((size_t)(b * NH + h) * NL + gi) * NL + jt;
                *(float4*)&wrow[tx * 4] =
                    make_float4(e[0] * uv[0], e[1] * uv[1], e[2] * uv[2], e[3] * uv[3]);
                *(float4*)&wrow[tx * 4 + 64] =
                    make_float4(e[4] * uv[4], e[5] * uv[5], e[6] * uv[6], e[7] * uv[7]);
            }
        }
    }
    // reduce row sums across the 16 tx threads (xor 1,2,4,8 stays in 16-group)
    #pragma unroll
    for (int ai = 0; ai < 8; ai++) {
        #pragma unroll
        for (int o = 8; o > 0; o >>= 1)
            rs[ai] += __shfl_xor_sync(0xffffffffu, rs[ai], o);
    }
    if (tx == 0) {
        #pragma unroll
        for (int ai = 0; ai < 8; ai++) {
            int gi = i0 + (ai >> 2) * 64 + ty * 4 + (ai & 3);
            g_irs[(size_t)(b * NH + h) * NL + gi] = 1.f / rs[ai];
        }
    }
}

// ---------------- kernel E: s[j] = sum_h irs[h]*ew[h,i,j]; force = r @ s + bo ----
__global__ void __launch_bounds__(128) k_out(const float* __restrict__ r,
                                             const float* __restrict__ bo,
                                             float* __restrict__ out) {
    int bi = blockIdx.x;
    int b = bi >> 9, i = bi & (NL - 1);
    __shared__ float4 s4[NL / 4];
    __shared__ float irs_s[NH];
    __shared__ float red[3][4];
    int tid = threadIdx.x;
    if (tid < NH) irs_s[tid] = g_irs[(size_t)(b * NH + tid) * NL + i];
    __syncthreads();

    const float* wbase = g_w + ((size_t)(b * NH) * NL + i) * NL;
    float4 a = make_float4(0.f, 0.f, 0.f, 0.f);
    #pragma unroll
    for (int h = 0; h < NH; h++) {
        float4 wv4 = ((const float4*)(wbase + (size_t)h * NL * NL))[tid];
        float ir = irs_s[h];
        a.x += ir * wv4.x; a.y += ir * wv4.y;
        a.z += ir * wv4.z; a.w += ir * wv4.w;
    }
    s4[tid] = a;
    __syncthreads();

    float p[3];
    #pragma unroll
    for (int c = 0; c < 3; c++) {
        const float4* rr = (const float4*)(r + ((size_t)(b * 3 + c) * NL + i) * NL);
        float4 rv = rr[tid];
        float4 sv = s4[tid];
        p[c] = rv.x * sv.x + rv.y * sv.y + rv.z * sv.z + rv.w * sv.w;
    }
    int lane = tid & 31, wrp = tid >> 5;
    #pragma unroll
    for (int c = 0; c < 3; c++) {
        #pragma unroll
        for (int o = 16; o > 0; o >>= 1)
            p[c] += __shfl_xor_sync(0xffffffffu, p[c], o);
        if (lane == 0) red[c][wrp] = p[c];
    }
    __syncthreads();
    if (tid < 3)
        out[bi * 3 + tid] = red[tid][0] + red[tid][1] + red[tid][2] + red[tid][3] + bo[0];
}

// ---------------- launch ----------------
extern "C" void kernel_launch(void* const* d_in, const int* in_sizes, int n_in,
                              void* d_out, int out_size) {
    const float* x    = (const float*)d_in[0];
    const float* r    = (const float*)d_in[1];
    const float* bias = (const float*)d_in[2];
    const int*   mask = (const int*)d_in[3];
    const float* wq   = (const float*)d_in[4];
    const float* bq   = (const float*)d_in[5];
    const float* wk   = (const float*)d_in[6];
    const float* bk   = (const float*)d_in[7];
    const float* wv   = (const float*)d_in[8];
    const float* bv   = (const float*)d_in[9];
    const float* wo   = (const float*)d_in[10];
    const float* bo   = (const float*)d_in[11];
    float* out = (float*)d_out;

    const int attn_smem = (2 * HD * APAD) * 4;   // 67,584 B
    cudaFuncSetAttribute(k_attn, cudaFuncAttributeMaxDynamicSharedMemorySize, attn_smem);

    k_wvo<<<dim3(NH, 4), 256>>>(wv, wo, bv);
    k_u<<<BSZ * NL, 512>>>(x);
    k_proj<<<dim3(DM / BN, (BSZ * NL) / BM, 2), 256>>>(x, wq, bq, wk, bk);
    k_attn<<<dim3(NL / 128, NH, BSZ), 256, attn_smem>>>(bias, mask);
    k_out<<<BSZ * NL, 128>>>(r, bo, out);
}

// round 10
// speedup vs baseline: 3.7994x; 1.4609x over previous
#include <cuda_runtime.h>
#include <cuda_bf16.h>
#include <math.h>
#include <stdint.h>

#define BSZ 4
#define NL  512
#define DM  1024
#define NH  16
#define HD  64

// ---------------- scratch (static device globals; no allocation) ----------------
__device__ float g_q[BSZ*NH*NL*HD];        // [b,h,i,d]  8 MB
__device__ float g_k[BSZ*NH*NL*HD];        // [b,h,j,d]  8 MB
__device__ float g_w[BSZ*NH*NL*NL];        // ew[b,h,i,j] = exp(logit)*u[h,j]  64 MB
__device__ float g_irs[BSZ*NH*NL];         // 1/rowsum[b,h,i]
__device__ float g_u[BSZ*NH*NL];           // u[b,h,j]
__device__ float g_wvo[NH*DM];             // wvo[h][din]
__device__ float g_bvo[NH];
// split-bf16 operands for tensor-core projections
__device__ __nv_bfloat16 g_xhi[BSZ*NL*DM];     // x hi  [m][k]
__device__ __nv_bfloat16 g_xlo[BSZ*NL*DM];     // x lo
__device__ __nv_bfloat16 g_wthi[2*DM*DM];      // W^T hi [which][n][k]
__device__ __nv_bfloat16 g_wtlo[2*DM*DM];      // W^T lo

// ============================ HMMA helpers (arch-portable PTX) ============================
__device__ __forceinline__ uint32_t smem_u32(const void* p) {
    uint32_t a;
    asm("{ .reg .u64 t; cvta.to.shared.u64 t, %1; cvt.u32.u64 %0, t; }" : "=r"(a) : "l"(p));
    return a;
}
__device__ __forceinline__ void ldsm_x4(uint32_t& r0, uint32_t& r1, uint32_t& r2, uint32_t& r3,
                                        uint32_t addr) {
    asm volatile("ldmatrix.sync.aligned.m8n8.x4.shared.b16 {%0,%1,%2,%3}, [%4];"
                 : "=r"(r0), "=r"(r1), "=r"(r2), "=r"(r3) : "r"(addr));
}
__device__ __forceinline__ void ldsm_x2(uint32_t& r0, uint32_t& r1, uint32_t addr) {
    asm volatile("ldmatrix.sync.aligned.m8n8.x2.shared.b16 {%0,%1}, [%2];"
                 : "=r"(r0), "=r"(r1) : "r"(addr));
}
__device__ __forceinline__ void mma_bf16(float* d, const uint32_t* a, const uint32_t* b) {
    asm volatile("mma.sync.aligned.m16n8k16.row.col.f32.bf16.bf16.f32 "
                 "{%0,%1,%2,%3}, {%4,%5,%6,%7}, {%8,%9}, {%0,%1,%2,%3};"
                 : "+f"(d[0]), "+f"(d[1]), "+f"(d[2]), "+f"(d[3])
                 : "r"(a[0]), "r"(a[1]), "r"(a[2]), "r"(a[3]), "r"(b[0]), "r"(b[1]));
}

// ---------------- prep: split x into bf16 hi/lo ----------------
__global__ void __launch_bounds__(256) k_split_x(const float* __restrict__ x) {
    int t = blockIdx.x * 256 + threadIdx.x;        // one float4 per thread
    float4 v = ((const float4*)x)[t];
    float vv[4] = {v.x, v.y, v.z, v.w};
    __nv_bfloat16 hi[4], lo[4];
    #pragma unroll
    for (int i = 0; i < 4; i++) {
        hi[i] = __float2bfloat16(vv[i]);
        lo[i] = __float2bfloat16(vv[i] - __bfloat162float(hi[i]));
    }
    __nv_bfloat162* ph = (__nv_bfloat162*)g_xhi;
    __nv_bfloat162* pl = (__nv_bfloat162*)g_xlo;
    ph[t*2]   = __nv_bfloat162(hi[0], hi[1]);
    ph[t*2+1] = __nv_bfloat162(hi[2], hi[3]);
    pl[t*2]   = __nv_bfloat162(lo[0], lo[1]);
    pl[t*2+1] = __nv_bfloat162(lo[2], lo[3]);
}

// ---------------- prep: transpose + split wq/wk -> W^T hi/lo ----------------
__global__ void __launch_bounds__(256) k_split_w(const float* __restrict__ wq,
                                                 const float* __restrict__ wk) {
    __shared__ float tile[32][33];
    int which = blockIdx.z;
    const float* src = which ? wk : wq;            // src[k][n]
    int k0 = blockIdx.y * 32, n0 = blockIdx.x * 32;
    int tx = threadIdx.x & 31, ty = threadIdx.x >> 5;   // 32 x 8
    #pragma unroll
    for (int i = 0; i < 4; i++)
        tile[ty + 8*i][tx] = src[(size_t)(k0 + ty + 8*i) * DM + n0 + tx];
    __syncthreads();
    size_t base = (size_t)which * DM * DM;
    #pragma unroll
    for (int i = 0; i < 4; i++) {
        float v = tile[tx][ty + 8*i];
        __nv_bfloat16 hi = __float2bfloat16(v);
        __nv_bfloat16 lo = __float2bfloat16(v - __bfloat162float(hi));
        size_t idx = base + (size_t)(n0 + ty + 8*i) * DM + k0 + tx;
        g_wthi[idx] = hi;
        g_wtlo[idx] = lo;
    }
}

// ---------------- kernel C: Q/K projection via mma.sync (split-bf16, fp32 accum) ----
// 128x128 block tile, 8 warps (2m x 4n), warp tile 64x32, BK=32, double-buffered.
// smem row pitch 40 bf16 (80 B) -> conflict-free ldmatrix.
#define PITCH   40
#define T_BYTES (128 * PITCH * 2)     // 10240 B per tile
#define OA_HI   0
#define OA_LO   (T_BYTES)
#define OB_HI   (2 * T_BYTES)
#define OB_LO   (3 * T_BYTES)
#define BUF_B   (4 * T_BYTES)         // 40960 B per buffer
#define HMMA_SMEM (2 * BUF_B)         // 81920 B
__global__ void __launch_bounds__(256) k_proj_hmma(const float* __restrict__ bq,
                                                   const float* __restrict__ bk) {
    extern __shared__ char smem[];
    uint32_t sb = smem_u32(smem);
    int tid = threadIdx.x, lane = tid & 31, wid = tid >> 5;
    int which = blockIdx.z;
    const __nv_bfloat16* Bh = g_wthi + (size_t)which * DM * DM;
    const __nv_bfloat16* Bl = g_wtlo + (size_t)which * DM * DM;
    float* out = which ? g_k : g_q;
    const float* bvec = which ? bk : bq;
    int m0 = blockIdx.y * 128, n0 = blockIdx.x * 128;
    int warp_m = wid & 1, warp_n = wid >> 1;       // 2 x 4
    int wm_base = warp_m * 64, wn_base = warp_n * 32;

    float acc[4][4][4];
    #pragma unroll
    for (int mi = 0; mi < 4; mi++)
        #pragma unroll
        for (int ni = 0; ni < 4; ni++)
            #pragma unroll
            for (int e = 0; e < 4; e++) acc[mi][ni][e] = 0.f;

    // loader mapping: 512 uint4-chunks per tile; 2 per thread
    int l_row[2], l_c8[2];
    #pragma unroll
    for (int t = 0; t < 2; t++) { int f = tid + t * 256; l_row[t] = f >> 2; l_c8[t] = f & 3; }

    uint4 rah[2], ral[2], rbh[2], rbl[2];
    auto load_regs = [&](int c) {
        int k0 = c * 32;
        #pragma unroll
        for (int t = 0; t < 2; t++) {
            size_t ga = (size_t)(m0 + l_row[t]) * DM + k0 + l_c8[t] * 8;
            size_t gb = (size_t)(n0 + l_row[t]) * DM + k0 + l_c8[t] * 8;
            rah[t] = *(const uint4*)(g_xhi + ga);
            ral[t] = *(const uint4*)(g_xlo + ga);
            rbh[t] = *(const uint4*)(Bh + gb);
            rbl[t] = *(const uint4*)(Bl + gb);
        }
    };
    auto store_smem = [&](int buf) {
        char* base = smem + buf * BUF_B;
        #pragma unroll
        for (int t = 0; t < 2; t++) {
            uint32_t off = (uint32_t)(l_row[t] * (PITCH * 2) + l_c8[t] * 16);
            *(uint4*)(base + OA_HI + off) = rah[t];
            *(uint4*)(base + OA_LO + off) = ral[t];
            *(uint4*)(base + OB_HI + off) = rbh[t];
            *(uint4*)(base + OB_LO + off) = rbl[t];
        }
    };

    load_regs(0);
    store_smem(0);
    __syncthreads();

    int buf = 0;
    for (int c = 0; c < 32; c++) {
        if (c < 31) load_regs(c + 1);
        uint32_t bb = sb + buf * BUF_B;
        #pragma unroll
        for (int ks = 0; ks < 2; ks++) {
            uint32_t ah[4][4], al[4][4], bh[4][2], bl[4][2];
            #pragma unroll
            for (int mi = 0; mi < 4; mi++) {
                uint32_t ro = (uint32_t)((wm_base + mi * 16 + (lane & 15)) * (PITCH * 2)
                              + (lane >> 4) * 16 + ks * 32);
                ldsm_x4(ah[mi][0], ah[mi][1], ah[mi][2], ah[mi][3], bb + OA_HI + ro);
                ldsm_x4(al[mi][0], al[mi][1], al[mi][2], al[mi][3], bb + OA_LO + ro);
            }
            #pragma unroll
            for (int ni = 0; ni < 4; ni++) {
                uint32_t ro = (uint32_t)((wn_base + ni * 8 + (lane & 7)) * (PITCH * 2)
                              + ((lane >> 3) & 1) * 16 + ks * 32);
                ldsm_x2(bh[ni][0], bh[ni][1], bb + OB_HI + ro);
                ldsm_x2(bl[ni][0], bl[ni][1], bb + OB_LO + ro);
            }
            #pragma unroll
            for (int mi = 0; mi < 4; mi++)
                #pragma unroll
                for (int ni = 0; ni < 4; ni++) {
                    mma_bf16(acc[mi][ni], ah[mi], bh[ni]);
                    mma_bf16(acc[mi][ni], ah[mi], bl[ni]);
                    mma_bf16(acc[mi][ni], al[mi], bh[ni]);
                }
        }
        if (c < 31) {
            store_smem(buf ^ 1);
            __syncthreads();
            buf ^= 1;
        }
    }

    // epilogue: acc fragment (groupID = lane>>2, qc = (lane&3)*2)
    int groupID = lane >> 2, qc = (lane & 3) * 2;
    #pragma unroll
    for (int mi = 0; mi < 4; mi++) {
        int m_lo = m0 + wm_base + mi * 16 + groupID;
        #pragma unroll
        for (int half = 0; half < 2; half++) {
            int m = m_lo + half * 8;
            int b = m >> 9, ii = m & (NL - 1);
            #pragma unroll
            for (int ni = 0; ni < 4; ni++) {
                int n = n0 + wn_base + ni * 8 + qc;
                int h = n >> 6, d = n & 63;
                float2 v;
                v.x = acc[mi][ni][half * 2 + 0] + bvec[n];
                v.y = acc[mi][ni][half * 2 + 1] + bvec[n + 1];
                *(float2*)(out + (((size_t)(b * NH + h) * NL + ii) * HD + d)) = v;
            }
        }
    }
}

// ---------------- kernel A: fold wo into wv -> wvo (1024x16) ----------------
__global__ void __launch_bounds__(256) k_wvo(const float* __restrict__ wv,
                                             const float* __restrict__ wo,
                                             const float* __restrict__ bv) {
    int h = blockIdx.x;
    int din = blockIdx.y * 256 + threadIdx.x;
    const float* wvrow = wv + (size_t)din * DM + h * HD;
    const float* worow = wo + h * HD;
    float acc = 0.f;
    #pragma unroll
    for (int e = 0; e < HD; e++) acc += wvrow[e] * worow[e];
    g_wvo[h * DM + din] = acc;
    if (din == 0) {
        float bb = 0.f;
        #pragma unroll
        for (int e = 0; e < HD; e++) bb += bv[h * HD + e] * worow[e];
        g_bvo[h] = bb;
    }
}

// ---------------- kernel B: u[b,h,j] = x[b,j,:] @ wvo[h,:] + bvo[h] ----------------
__global__ void __launch_bounds__(512) k_u(const float* __restrict__ x) {
    int bj = blockIdx.x;
    __shared__ float xs[DM];
    int tid = threadIdx.x;
    if (tid < 256) ((float4*)xs)[tid] = ((const float4*)(x + (size_t)bj * DM))[tid];
    __syncthreads();
    int h = tid >> 5;
    int lane = tid & 31;
    const float* wr = g_wvo + h * DM;
    float acc = 0.f;
    #pragma unroll 8
    for (int t = lane; t < DM; t += 32) acc += xs[t] * wr[t];
    #pragma unroll
    for (int o = 16; o > 0; o >>= 1) acc += __shfl_xor_sync(0xffffffffu, acc, o);
    if (lane == 0) {
        int b = bj >> 9, j = bj & (NL - 1);
        g_u[(b * NH + h) * NL + j] = acc + g_bvo[h];
    }
}

// ---------------- kernel D: logits -> exp (no max pass) -> ew + rowsums ----------
#define APAD 132
__global__ void __launch_bounds__(256, 2) k_attn(const float* __restrict__ bias,
                                                 const int* __restrict__ mask) {
    extern __shared__ float sm[];
    float* qs = sm;                        // [d][i], pitch APAD (pre-scaled)
    float* ks = sm + HD * APAD;            // [d][j], pitch APAD

    int b = blockIdx.z, h = blockIdx.y, i0 = blockIdx.x * 128;
    int tid = threadIdx.x;
    const float* qg = g_q + ((size_t)(b * NH + h) * NL + i0) * HD;
    const float* kg = g_k + (size_t)(b * NH + h) * NL * HD;
    const float* urow = g_u + (size_t)(b * NH + h) * NL;
    const float scale = 0.125f;

    {
        int rr = tid >> 1, c0 = (tid & 1) * 32;
        #pragma unroll
        for (int c4 = 0; c4 < 8; c4++) {
            float4 v = *(const float4*)&qg[rr * HD + c0 + c4 * 4];
            qs[(c0 + c4 * 4 + 0) * APAD + rr] = v.x * scale;
            qs[(c0 + c4 * 4 + 1) * APAD + rr] = v.y * scale;
            qs[(c0 + c4 * 4 + 2) * APAD + rr] = v.z * scale;
            qs[(c0 + c4 * 4 + 3) * APAD + rr] = v.w * scale;
        }
    }
    int tx = tid & 15, ty = tid >> 4;
    float rs[8] = {0.f, 0.f, 0.f, 0.f, 0.f, 0.f, 0.f, 0.f};

    for (int jt = 0; jt < NL; jt += 128) {
        __syncthreads();
        {
            int rr = tid >> 1, c0 = (tid & 1) * 32;
            #pragma unroll
            for (int c4 = 0; c4 < 8; c4++) {
                float4 v = *(const float4*)&kg[(jt + rr) * HD + c0 + c4 * 4];
                ks[(c0 + c4 * 4 + 0) * APAD + rr] = v.x;
                ks[(c0 + c4 * 4 + 1) * APAD + rr] = v.y;
                ks[(c0 + c4 * 4 + 2) * APAD + rr] = v.z;
                ks[(c0 + c4 * 4 + 3) * APAD + rr] = v.w;
            }
        }
        __syncthreads();
        float acc[8][8];
        #pragma unroll
        for (int i = 0; i < 8; i++)
            #pragma unroll
            for (int j = 0; j < 8; j++) acc[i][j] = 0.f;
        #pragma unroll 2
        for (int d = 0; d < HD; d++) {
            float av[8], bvv[8];
            *(float4*)&av[0]  = *(const float4*)&qs[d * APAD + ty * 4];
            *(float4*)&av[4]  = *(const float4*)&qs[d * APAD + ty * 4 + 64];
            *(float4*)&bvv[0] = *(const float4*)&ks[d * APAD + tx * 4];
            *(float4*)&bvv[4] = *(const float4*)&ks[d * APAD + tx * 4 + 64];
            #pragma unroll
            for (int i = 0; i < 8; i++)
                #pragma unroll
                for (int j = 0; j < 8; j++)
                    acc[i][j] += av[i] * bvv[j];
        }
        float uv[8];
        #pragma unroll
        for (int c = 0; c < 4; c++) {
            uv[c]     = urow[jt + tx * 4 + c];
            uv[c + 4] = urow[jt + tx * 4 + 64 + c];
        }
        #pragma unroll
        for (int ih = 0; ih < 2; ih++) {
            #pragma unroll
            for (int i = 0; i < 4; i++) {
                int ai = ih * 4 + i;
                int gi = i0 + ih * 64 + ty * 4 + i;
                const float* brow = bias + ((size_t)(b * NH + h) * NL + gi) * NL + jt;
                const int*   mrow = mask + ((size_t)b * NL + gi) * NL + jt;
                float4 bb0 = *(const float4*)&brow[tx * 4];
                float4 bb1 = *(const float4*)&brow[tx * 4 + 64];
                int4   mm0 = *(const int4*)&mrow[tx * 4];
                int4   mm1 = *(const int4*)&mrow[tx * 4 + 64];
                float e[8];
                e[0] = mm0.x ? __expf(acc[ai][0] + bb0.x) : 0.f;
                e[1] = mm0.y ? __expf(acc[ai][1] + bb0.y) : 0.f;
                e[2] = mm0.z ? __expf(acc[ai][2] + bb0.z) : 0.f;
                e[3] = mm0.w ? __expf(acc[ai][3] + bb0.w) : 0.f;
                e[4] = mm1.x ? __expf(acc[ai][4] + bb1.x) : 0.f;
                e[5] = mm1.y ? __expf(acc[ai][5] + bb1.y) : 0.f;
                e[6] = mm1.z ? __expf(acc[ai][6] + bb1.z) : 0.f;
                e[7] = mm1.w ? __expf(acc[ai][7] + bb1.w) : 0.f;
                rs[ai] += ((e[0] + e[1]) + (e[2] + e[3])) +
                          ((e[4] + e[5]) + (e[6] + e[7]));
                float* wrow = g_w + ((size_t)(b * NH + h) * NL + gi) * NL + jt;
                *(float4*)&wrow[tx * 4] =
                    make_float4(e[0] * uv[0], e[1] * uv[1], e[2] * uv[2], e[3] * uv[3]);
                *(float4*)&wrow[tx * 4 + 64] =
                    make_float4(e[4] * uv[4], e[5] * uv[5], e[6] * uv[6], e[7] * uv[7]);
            }
        }
    }
    #pragma unroll
    for (int ai = 0; ai < 8; ai++) {
        #pragma unroll
        for (int o = 8; o > 0; o >>= 1)
            rs[ai] += __shfl_xor_sync(0xffffffffu, rs[ai], o);
    }
    if (tx == 0) {
        #pragma unroll
        for (int ai = 0; ai < 8; ai++) {
            int gi = i0 + (ai >> 2) * 64 + ty * 4 + (ai & 3);
            g_irs[(size_t)(b * NH + h) * NL + gi] = 1.f / rs[ai];
        }
    }
}

// ---------------- kernel E: s[j] = sum_h irs[h]*ew[h,i,j]; force = r @ s + bo ----
__global__ void __launch_bounds__(128) k_out(const float* __restrict__ r,
                                             const float* __restrict__ bo,
                                             float* __restrict__ out) {
    int bi = blockIdx.x;
    int b = bi >> 9, i = bi & (NL - 1);
    __shared__ float4 s4[NL / 4];
    __shared__ float irs_s[NH];
    __shared__ float red[3][4];
    int tid = threadIdx.x;
    if (tid < NH) irs_s[tid] = g_irs[(size_t)(b * NH + tid) * NL + i];
    __syncthreads();

    const float* wbase = g_w + ((size_t)(b * NH) * NL + i) * NL;
    float4 a = make_float4(0.f, 0.f, 0.f, 0.f);
    #pragma unroll
    for (int h = 0; h < NH; h++) {
        float4 wv4 = ((const float4*)(wbase + (size_t)h * NL * NL))[tid];
        float ir = irs_s[h];
        a.x += ir * wv4.x; a.y += ir * wv4.y;
        a.z += ir * wv4.z; a.w += ir * wv4.w;
    }
    s4[tid] = a;
    __syncthreads();

    float p[3];
    #pragma unroll
    for (int c = 0; c < 3; c++) {
        const float4* rr = (const float4*)(r + ((size_t)(b * 3 + c) * NL + i) * NL);
        float4 rv = rr[tid];
        float4 sv = s4[tid];
        p[c] = rv.x * sv.x + rv.y * sv.y + rv.z * sv.z + rv.w * sv.w;
    }
    int lane = tid & 31, wrp = tid >> 5;
    #pragma unroll
    for (int c = 0; c < 3; c++) {
        #pragma unroll
        for (int o = 16; o > 0; o >>= 1)
            p[c] += __shfl_xor_sync(0xffffffffu, p[c], o);
        if (lane == 0) red[c][wrp] = p[c];
    }
    __syncthreads();
    if (tid < 3)
        out[bi * 3 + tid] = red[tid][0] + red[tid][1] + red[tid][2] + red[tid][3] + bo[0];
}

// ---------------- launch ----------------
extern "C" void kernel_launch(void* const* d_in, const int* in_sizes, int n_in,
                              void* d_out, int out_size) {
    const float* x    = (const float*)d_in[0];
    const float* r    = (const float*)d_in[1];
    const float* bias = (const float*)d_in[2];
    const int*   mask = (const int*)d_in[3];
    const float* wq   = (const float*)d_in[4];
    const float* bq   = (const float*)d_in[5];
    const float* wk   = (const float*)d_in[6];
    const float* bk   = (const float*)d_in[7];
    const float* wv   = (const float*)d_in[8];
    const float* bv   = (const float*)d_in[9];
    const float* wo   = (const float*)d_in[10];
    const float* bo   = (const float*)d_in[11];
    float* out = (float*)d_out;

    const int attn_smem = (2 * HD * APAD) * 4;   // 67,584 B
    cudaFuncSetAttribute(k_attn, cudaFuncAttributeMaxDynamicSharedMemorySize, attn_smem);
    cudaFuncSetAttribute(k_proj_hmma, cudaFuncAttributeMaxDynamicSharedMemorySize, HMMA_SMEM);

    k_split_x<<<BSZ * NL * DM / 1024, 256>>>(x);
    k_split_w<<<dim3(DM / 32, DM / 32, 2), 256>>>(wq, wk);
    k_wvo<<<dim3(NH, 4), 256>>>(wv, wo, bv);
    k_u<<<BSZ * NL, 512>>>(x);
    k_proj_hmma<<<dim3(DM / 128, (BSZ * NL) / 128, 2), 256, HMMA_SMEM>>>(bq, bk);
    k_attn<<<dim3(NL / 128, NH, BSZ), 256, attn_smem>>>(bias, mask);
    k_out<<<BSZ * NL, 128>>>(r, bo, out);
}

// round 11
// speedup vs baseline: 3.9921x; 1.0507x over previous
#include <cuda_runtime.h>
#include <cuda_bf16.h>
#include <math.h>
#include <stdint.h>

#define BSZ 4
#define NL  512
#define DM  1024
#define NH  16
#define HD  64

// ---------------- scratch (static device globals; no allocation) ----------------
__device__ float g_w[BSZ*NH*NL*NL];        // ew[b,h,i,j] = exp(logit)*u[h,j]  64 MB
__device__ float g_irs[BSZ*NH*NL];         // 1/rowsum[b,h,i]
__device__ float g_u[BSZ*NH*NL];           // u[b,h,j]
__device__ float g_wvo[NH*DM];             // wvo[h][din]
__device__ float g_bvo[NH];
// split-bf16 operands
__device__ __nv_bfloat16 g_xhi[BSZ*NL*DM];     // x hi  [m][k]
__device__ __nv_bfloat16 g_xlo[BSZ*NL*DM];     // x lo
__device__ __nv_bfloat16 g_wthi[2*DM*DM];      // W^T hi [which][n][k]
__device__ __nv_bfloat16 g_wtlo[2*DM*DM];      // W^T lo
__device__ __nv_bfloat16 g_qhi[BSZ*NH*NL*HD];  // q/8 hi [b,h,i,d]
__device__ __nv_bfloat16 g_qlo[BSZ*NH*NL*HD];
__device__ __nv_bfloat16 g_khi[BSZ*NH*NL*HD];  // k hi   [b,h,j,d]
__device__ __nv_bfloat16 g_klo[BSZ*NH*NL*HD];

// ============================ HMMA helpers (arch-portable PTX) ============================
__device__ __forceinline__ uint32_t smem_u32(const void* p) {
    uint32_t a;
    asm("{ .reg .u64 t; cvta.to.shared.u64 t, %1; cvt.u32.u64 %0, t; }" : "=r"(a) : "l"(p));
    return a;
}
__device__ __forceinline__ void ldsm_x4(uint32_t& r0, uint32_t& r1, uint32_t& r2, uint32_t& r3,
                                        uint32_t addr) {
    asm volatile("ldmatrix.sync.aligned.m8n8.x4.shared.b16 {%0,%1,%2,%3}, [%4];"
                 : "=r"(r0), "=r"(r1), "=r"(r2), "=r"(r3) : "r"(addr));
}
__device__ __forceinline__ void ldsm_x2(uint32_t& r0, uint32_t& r1, uint32_t addr) {
    asm volatile("ldmatrix.sync.aligned.m8n8.x2.shared.b16 {%0,%1}, [%2];"
                 : "=r"(r0), "=r"(r1) : "r"(addr));
}
__device__ __forceinline__ void mma_bf16(float* d, const uint32_t* a, const uint32_t* b) {
    asm volatile("mma.sync.aligned.m16n8k16.row.col.f32.bf16.bf16.f32 "
                 "{%0,%1,%2,%3}, {%4,%5,%6,%7}, {%8,%9}, {%0,%1,%2,%3};"
                 : "+f"(d[0]), "+f"(d[1]), "+f"(d[2]), "+f"(d[3])
                 : "r"(a[0]), "r"(a[1]), "r"(a[2]), "r"(a[3]), "r"(b[0]), "r"(b[1]));
}
__device__ __forceinline__ void split_bf16(float v, __nv_bfloat16& hi, __nv_bfloat16& lo) {
    hi = __float2bfloat16(v);
    lo = __float2bfloat16(v - __bfloat162float(hi));
}

// ---------------- prep: split x into bf16 hi/lo ----------------
__global__ void __launch_bounds__(256) k_split_x(const float* __restrict__ x) {
    int t = blockIdx.x * 256 + threadIdx.x;
    float4 v = ((const float4*)x)[t];
    float vv[4] = {v.x, v.y, v.z, v.w};
    __nv_bfloat16 hi[4], lo[4];
    #pragma unroll
    for (int i = 0; i < 4; i++) split_bf16(vv[i], hi[i], lo[i]);
    __nv_bfloat162* ph = (__nv_bfloat162*)g_xhi;
    __nv_bfloat162* pl = (__nv_bfloat162*)g_xlo;
    ph[t*2]   = __nv_bfloat162(hi[0], hi[1]);
    ph[t*2+1] = __nv_bfloat162(hi[2], hi[3]);
    pl[t*2]   = __nv_bfloat162(lo[0], lo[1]);
    pl[t*2+1] = __nv_bfloat162(lo[2], lo[3]);
}

// ---------------- prep: transpose + split wq/wk -> W^T hi/lo ----------------
__global__ void __launch_bounds__(256) k_split_w(const float* __restrict__ wq,
                                                 const float* __restrict__ wk) {
    __shared__ float tile[32][33];
    int which = blockIdx.z;
    const float* src = which ? wk : wq;            // src[k][n]
    int k0 = blockIdx.y * 32, n0 = blockIdx.x * 32;
    int tx = threadIdx.x & 31, ty = threadIdx.x >> 5;
    #pragma unroll
    for (int i = 0; i < 4; i++)
        tile[ty + 8*i][tx] = src[(size_t)(k0 + ty + 8*i) * DM + n0 + tx];
    __syncthreads();
    size_t base = (size_t)which * DM * DM;
    #pragma unroll
    for (int i = 0; i < 4; i++) {
        float v = tile[tx][ty + 8*i];
        __nv_bfloat16 hi, lo;
        split_bf16(v, hi, lo);
        size_t idx = base + (size_t)(n0 + ty + 8*i) * DM + k0 + tx;
        g_wthi[idx] = hi;
        g_wtlo[idx] = lo;
    }
}

// ---------------- kernel C: Q/K projection via mma.sync -> split-bf16 q/k ----------
#define PITCH   40
#define T_BYTES (128 * PITCH * 2)
#define OA_HI   0
#define OA_LO   (T_BYTES)
#define OB_HI   (2 * T_BYTES)
#define OB_LO   (3 * T_BYTES)
#define BUF_B   (4 * T_BYTES)
#define HMMA_SMEM (2 * BUF_B)
__global__ void __launch_bounds__(256) k_proj_hmma(const float* __restrict__ bq,
                                                   const float* __restrict__ bk) {
    extern __shared__ char smem[];
    uint32_t sb = smem_u32(smem);
    int tid = threadIdx.x, lane = tid & 31, wid = tid >> 5;
    int which = blockIdx.z;
    const __nv_bfloat16* Bh = g_wthi + (size_t)which * DM * DM;
    const __nv_bfloat16* Bl = g_wtlo + (size_t)which * DM * DM;
    __nv_bfloat16* ohi = which ? g_khi : g_qhi;
    __nv_bfloat16* olo = which ? g_klo : g_qlo;
    const float* bvec = which ? bk : bq;
    const float oscale = which ? 1.0f : 0.125f;    // fold 1/sqrt(64) into q
    int m0 = blockIdx.y * 128, n0 = blockIdx.x * 128;
    int warp_m = wid & 1, warp_n = wid >> 1;
    int wm_base = warp_m * 64, wn_base = warp_n * 32;

    float acc[4][4][4];
    #pragma unroll
    for (int mi = 0; mi < 4; mi++)
        #pragma unroll
        for (int ni = 0; ni < 4; ni++)
            #pragma unroll
            for (int e = 0; e < 4; e++) acc[mi][ni][e] = 0.f;

    int l_row[2], l_c8[2];
    #pragma unroll
    for (int t = 0; t < 2; t++) { int f = tid + t * 256; l_row[t] = f >> 2; l_c8[t] = f & 3; }

    uint4 rah[2], ral[2], rbh[2], rbl[2];
    auto load_regs = [&](int c) {
        int k0 = c * 32;
        #pragma unroll
        for (int t = 0; t < 2; t++) {
            size_t ga = (size_t)(m0 + l_row[t]) * DM + k0 + l_c8[t] * 8;
            size_t gb = (size_t)(n0 + l_row[t]) * DM + k0 + l_c8[t] * 8;
            rah[t] = *(const uint4*)(g_xhi + ga);
            ral[t] = *(const uint4*)(g_xlo + ga);
            rbh[t] = *(const uint4*)(Bh + gb);
            rbl[t] = *(const uint4*)(Bl + gb);
        }
    };
    auto store_smem = [&](int buf) {
        char* base = smem + buf * BUF_B;
        #pragma unroll
        for (int t = 0; t < 2; t++) {
            uint32_t off = (uint32_t)(l_row[t] * (PITCH * 2) + l_c8[t] * 16);
            *(uint4*)(base + OA_HI + off) = rah[t];
            *(uint4*)(base + OA_LO + off) = ral[t];
            *(uint4*)(base + OB_HI + off) = rbh[t];
            *(uint4*)(base + OB_LO + off) = rbl[t];
        }
    };

    load_regs(0);
    store_smem(0);
    __syncthreads();

    int buf = 0;
    for (int c = 0; c < 32; c++) {
        if (c < 31) load_regs(c + 1);
        uint32_t bb = sb + buf * BUF_B;
        #pragma unroll
        for (int ks = 0; ks < 2; ks++) {
            uint32_t ah[4][4], al[4][4], bh[4][2], bl[4][2];
            #pragma unroll
            for (int mi = 0; mi < 4; mi++) {
                uint32_t ro = (uint32_t)((wm_base + mi * 16 + (lane & 15)) * (PITCH * 2)
                              + (lane >> 4) * 16 + ks * 32);
                ldsm_x4(ah[mi][0], ah[mi][1], ah[mi][2], ah[mi][3], bb + OA_HI + ro);
                ldsm_x4(al[mi][0], al[mi][1], al[mi][2], al[mi][3], bb + OA_LO + ro);
            }
            #pragma unroll
            for (int ni = 0; ni < 4; ni++) {
                uint32_t ro = (uint32_t)((wn_base + ni * 8 + (lane & 7)) * (PITCH * 2)
                              + ((lane >> 3) & 1) * 16 + ks * 32);
                ldsm_x2(bh[ni][0], bh[ni][1], bb + OB_HI + ro);
                ldsm_x2(bl[ni][0], bl[ni][1], bb + OB_LO + ro);
            }
            #pragma unroll
            for (int mi = 0; mi < 4; mi++)
                #pragma unroll
                for (int ni = 0; ni < 4; ni++) {
                    mma_bf16(acc[mi][ni], ah[mi], bh[ni]);
                    mma_bf16(acc[mi][ni], ah[mi], bl[ni]);
                    mma_bf16(acc[mi][ni], al[mi], bh[ni]);
                }
        }
        if (c < 31) {
            store_smem(buf ^ 1);
            __syncthreads();
            buf ^= 1;
        }
    }

    // epilogue: +bias, scale (q only), split to bf16 hi/lo, scatter [b,h,i,d]
    int groupID = lane >> 2, qc = (lane & 3) * 2;
    #pragma unroll
    for (int mi = 0; mi < 4; mi++) {
        #pragma unroll
        for (int half = 0; half < 2; half++) {
            int m = m0 + wm_base + mi * 16 + groupID + half * 8;
            int b = m >> 9, ii = m & (NL - 1);
            #pragma unroll
            for (int ni = 0; ni < 4; ni++) {
                int n = n0 + wn_base + ni * 8 + qc;
                int h = n >> 6, d = n & 63;
                float vx = (acc[mi][ni][half * 2 + 0] + bvec[n])     * oscale;
                float vy = (acc[mi][ni][half * 2 + 1] + bvec[n + 1]) * oscale;
                __nv_bfloat16 hx, lx, hy, ly;
                split_bf16(vx, hx, lx);
                split_bf16(vy, hy, ly);
                size_t o = ((size_t)(b * NH + h) * NL + ii) * HD + d;
                *(__nv_bfloat162*)(ohi + o) = __nv_bfloat162(hx, hy);
                *(__nv_bfloat162*)(olo + o) = __nv_bfloat162(lx, ly);
            }
        }
    }
}

// ---------------- kernel A: fold wo into wv -> wvo (1024x16) ----------------
__global__ void __launch_bounds__(256) k_wvo(const float* __restrict__ wv,
                                             const float* __restrict__ wo,
                                             const float* __restrict__ bv) {
    int h = blockIdx.x;
    int din = blockIdx.y * 256 + threadIdx.x;
    const float* wvrow = wv + (size_t)din * DM + h * HD;
    const float* worow = wo + h * HD;
    float acc = 0.f;
    #pragma unroll
    for (int e = 0; e < HD; e++) acc += wvrow[e] * worow[e];
    g_wvo[h * DM + din] = acc;
    if (din == 0) {
        float bb = 0.f;
        #pragma unroll
        for (int e = 0; e < HD; e++) bb += bv[h * HD + e] * worow[e];
        g_bvo[h] = bb;
    }
}

// ---------------- kernel B: u[b,h,j] = x[b,j,:] @ wvo[h,:] + bvo[h] ----------------
__global__ void __launch_bounds__(512) k_u(const float* __restrict__ x) {
    int bj = blockIdx.x;
    __shared__ float xs[DM];
    int tid = threadIdx.x;
    if (tid < 256) ((float4*)xs)[tid] = ((const float4*)(x + (size_t)bj * DM))[tid];
    __syncthreads();
    int h = tid >> 5;
    int lane = tid & 31;
    const float* wr = g_wvo + h * DM;
    float acc = 0.f;
    #pragma unroll 8
    for (int t = lane; t < DM; t += 32) acc += xs[t] * wr[t];
    #pragma unroll
    for (int o = 16; o > 0; o >>= 1) acc += __shfl_xor_sync(0xffffffffu, acc, o);
    if (lane == 0) {
        int b = bj >> 9, j = bj & (NL - 1);
        g_u[(b * NH + h) * NL + j] = acc + g_bvo[h];
    }
}

// ---------------- kernel D: HMMA logits -> exp -> ew + rowsums ----------
// 128x128 i-tile x j-tile, 8 warps (2m x 4n), split-bf16 3-term mma.
#define QP 72                              // bf16 pitch (144 B rows, conflict-free)
#define AT_QHI 0
#define AT_QLO (128 * QP * 2)
#define AT_KHI (2 * 128 * QP * 2)
#define AT_KLO (3 * 128 * QP * 2)
#define ATTN_SMEM (4 * 128 * QP * 2)       // 73,728 B
__global__ void __launch_bounds__(256) k_attn(const float* __restrict__ bias,
                                              const int* __restrict__ mask) {
    extern __shared__ char smem[];
    __shared__ float rs_sm[4][128];
    uint32_t sb = smem_u32(smem);
    int tid = threadIdx.x, lane = tid & 31, wid = tid >> 5;
    int warp_m = wid & 1, warp_n = wid >> 1;
    int wm = warp_m * 64, wn = warp_n * 32;
    int b = blockIdx.z, h = blockIdx.y, i0 = blockIdx.x * 128;
    const __nv_bfloat16* qh = g_qhi + ((size_t)(b * NH + h) * NL + i0) * HD;
    const __nv_bfloat16* ql = g_qlo + ((size_t)(b * NH + h) * NL + i0) * HD;
    const __nv_bfloat16* kh = g_khi + (size_t)(b * NH + h) * NL * HD;
    const __nv_bfloat16* kl = g_klo + (size_t)(b * NH + h) * NL * HD;
    const float* urow = g_u + (size_t)(b * NH + h) * NL;

    // load q tile: 128 rows x 64 bf16 (128 B) -> pitch-144 smem
    #pragma unroll
    for (int t = 0; t < 4; t++) {
        int f = tid + t * 256;             // 1024 chunks
        int r = f >> 3, c = f & 7;
        *(uint4*)(smem + AT_QHI + r * (QP * 2) + c * 16) = *(const uint4*)(qh + r * HD + c * 8);
        *(uint4*)(smem + AT_QLO + r * (QP * 2) + c * 16) = *(const uint4*)(ql + r * HD + c * 8);
    }
    for (int idx = tid; idx < 512; idx += 256) ((float*)rs_sm)[idx] = 0.f;

    int groupID = lane >> 2, qc = (lane & 3) * 2;
    float rs8[8];
    #pragma unroll
    for (int i = 0; i < 8; i++) rs8[i] = 0.f;

    for (int jt = 0; jt < NL; jt += 128) {
        __syncthreads();
        #pragma unroll
        for (int t = 0; t < 4; t++) {
            int f = tid + t * 256;
            int r = f >> 3, c = f & 7;
            *(uint4*)(smem + AT_KHI + r * (QP * 2) + c * 16) =
                *(const uint4*)(kh + (size_t)(jt + r) * HD + c * 8);
            *(uint4*)(smem + AT_KLO + r * (QP * 2) + c * 16) =
                *(const uint4*)(kl + (size_t)(jt + r) * HD + c * 8);
        }
        __syncthreads();

        float acc[4][4][4];
        #pragma unroll
        for (int mi = 0; mi < 4; mi++)
            #pragma unroll
            for (int ni = 0; ni < 4; ni++)
                #pragma unroll
                for (int e = 0; e < 4; e++) acc[mi][ni][e] = 0.f;

        #pragma unroll
        for (int ks = 0; ks < 4; ks++) {
            uint32_t ah[4][4], al[4][4], bh[4][2], bl[4][2];
            #pragma unroll
            for (int mi = 0; mi < 4; mi++) {
                uint32_t ro = (uint32_t)((wm + mi * 16 + (lane & 15)) * (QP * 2)
                              + (lane >> 4) * 16 + ks * 32);
                ldsm_x4(ah[mi][0], ah[mi][1], ah[mi][2], ah[mi][3], sb + AT_QHI + ro);
                ldsm_x4(al[mi][0], al[mi][1], al[mi][2], al[mi][3], sb + AT_QLO + ro);
            }
            #pragma unroll
            for (int ni = 0; ni < 4; ni++) {
                uint32_t ro = (uint32_t)((wn + ni * 8 + (lane & 7)) * (QP * 2)
                              + ((lane >> 3) & 1) * 16 + ks * 32);
                ldsm_x2(bh[ni][0], bh[ni][1], sb + AT_KHI + ro);
                ldsm_x2(bl[ni][0], bl[ni][1], sb + AT_KLO + ro);
            }
            #pragma unroll
            for (int mi = 0; mi < 4; mi++)
                #pragma unroll
                for (int ni = 0; ni < 4; ni++) {
                    mma_bf16(acc[mi][ni], ah[mi], bh[ni]);
                    mma_bf16(acc[mi][ni], ah[mi], bl[ni]);
                    mma_bf16(acc[mi][ni], al[mi], bh[ni]);
                }
        }

        // epilogue: bias + mask + exp, fold u, accumulate row sums
        float2 uv2[4];
        #pragma unroll
        for (int ni = 0; ni < 4; ni++)
            uv2[ni] = *(const float2*)&urow[jt + wn + ni * 8 + qc];
        #pragma unroll
        for (int mi = 0; mi < 4; mi++) {
            #pragma unroll
            for (int half = 0; half < 2; half++) {
                int gi = i0 + wm + mi * 16 + groupID + half * 8;
                const float* brow = bias + ((size_t)(b * NH + h) * NL + gi) * NL + jt;
                const int*   mrow = mask + ((size_t)b * NL + gi) * NL + jt;
                float* wrow = g_w + ((size_t)(b * NH + h) * NL + gi) * NL + jt;
                float rloc = 0.f;
                #pragma unroll
                for (int ni = 0; ni < 4; ni++) {
                    int col = wn + ni * 8 + qc;
                    float2 bb = *(const float2*)&brow[col];
                    int2   mm = *(const int2*)&mrow[col];
                    float e0 = mm.x ? __expf(acc[mi][ni][half * 2 + 0] + bb.x) : 0.f;
                    float e1 = mm.y ? __expf(acc[mi][ni][half * 2 + 1] + bb.y) : 0.f;
                    rloc += e0 + e1;
                    *(float2*)&wrow[col] = make_float2(e0 * uv2[ni].x, e1 * uv2[ni].y);
                }
                rs8[mi * 2 + half] += rloc;
            }
        }
    }

    // reduce rs over quad lanes (cols), deposit per-warp_n partials, combine
    #pragma unroll
    for (int i = 0; i < 8; i++) {
        rs8[i] += __shfl_xor_sync(0xffffffffu, rs8[i], 1);
        rs8[i] += __shfl_xor_sync(0xffffffffu, rs8[i], 2);
    }
    if ((lane & 3) == 0) {
        #pragma unroll
        for (int mi = 0; mi < 4; mi++)
            #pragma unroll
            for (int half = 0; half < 2; half++)
                rs_sm[warp_n][wm + mi * 16 + groupID + half * 8] = rs8[mi * 2 + half];
    }
    __syncthreads();
    if (tid < 128) {
        float s = rs_sm[0][tid] + rs_sm[1][tid] + rs_sm[2][tid] + rs_sm[3][tid];
        g_irs[(size_t)(b * NH + h) * NL + i0 + tid] = 1.f / s;
    }
}

// ---------------- kernel E: s[j] = sum_h irs[h]*ew[h,i,j]; force = r @ s + bo ----
__global__ void __launch_bounds__(128) k_out(const float* __restrict__ r,
                                             const float* __restrict__ bo,
                                             float* __restrict__ out) {
    int bi = blockIdx.x;
    int b = bi >> 9, i = bi & (NL - 1);
    __shared__ float4 s4[NL / 4];
    __shared__ float irs_s[NH];
    __shared__ float red[3][4];
    int tid = threadIdx.x;
    if (tid < NH) irs_s[tid] = g_irs[(size_t)(b * NH + tid) * NL + i];
    __syncthreads();

    const float* wbase = g_w + ((size_t)(b * NH) * NL + i) * NL;
    float4 a = make_float4(0.f, 0.f, 0.f, 0.f);
    #pragma unroll
    for (int h = 0; h < NH; h++) {
        float4 wv4 = ((const float4*)(wbase + (size_t)h * NL * NL))[tid];
        float ir = irs_s[h];
        a.x += ir * wv4.x; a.y += ir * wv4.y;
        a.z += ir * wv4.z; a.w += ir * wv4.w;
    }
    s4[tid] = a;
    __syncthreads();

    float p[3];
    #pragma unroll
    for (int c = 0; c < 3; c++) {
        const float4* rr = (const float4*)(r + ((size_t)(b * 3 + c) * NL + i) * NL);
        float4 rv = rr[tid];
        float4 sv = s4[tid];
        p[c] = rv.x * sv.x + rv.y * sv.y + rv.z * sv.z + rv.w * sv.w;
    }
    int lane = tid & 31, wrp = tid >> 5;
    #pragma unroll
    for (int c = 0; c < 3; c++) {
        #pragma unroll
        for (int o = 16; o > 0; o >>= 1)
            p[c] += __shfl_xor_sync(0xffffffffu, p[c], o);
        if (lane == 0) red[c][wrp] = p[c];
    }
    __syncthreads();
    if (tid < 3)
        out[bi * 3 + tid] = red[tid][0] + red[tid][1] + red[tid][2] + red[tid][3] + bo[0];
}

// ---------------- launch ----------------
extern "C" void kernel_launch(void* const* d_in, const int* in_sizes, int n_in,
                              void* d_out, int out_size) {
    const float* x    = (const float*)d_in[0];
    const float* r    = (const float*)d_in[1];
    const float* bias = (const float*)d_in[2];
    const int*   mask = (const int*)d_in[3];
    const float* wq   = (const float*)d_in[4];
    const float* bq   = (const float*)d_in[5];
    const float* wk   = (const float*)d_in[6];
    const float* bk   = (const float*)d_in[7];
    const float* wv   = (const float*)d_in[8];
    const float* bv   = (const float*)d_in[9];
    const float* wo   = (const float*)d_in[10];
    const float* bo   = (const float*)d_in[11];
    float* out = (float*)d_out;

    cudaFuncSetAttribute(k_attn, cudaFuncAttributeMaxDynamicSharedMemorySize, ATTN_SMEM);
    cudaFuncSetAttribute(k_proj_hmma, cudaFuncAttributeMaxDynamicSharedMemorySize, HMMA_SMEM);

    k_split_x<<<BSZ * NL * DM / 1024, 256>>>(x);
    k_split_w<<<dim3(DM / 32, DM / 32, 2), 256>>>(wq, wk);
    k_wvo<<<dim3(NH, 4), 256>>>(wv, wo, bv);
    k_u<<<BSZ * NL, 512>>>(x);
    k_proj_hmma<<<dim3(DM / 128, (BSZ * NL) / 128, 2), 256, HMMA_SMEM>>>(bq, bk);
    k_attn<<<dim3(NL / 128, NH, BSZ), 256, ATTN_SMEM>>>(bias, mask);
    k_out<<<BSZ * NL, 128>>>(r, bo, out);
}